// round 5
// baseline (speedup 1.0000x reference)
#include <cuda_runtime.h>
#include <cuda_fp16.h>
#include <cstdint>

// Problem dims
constexpr int B_ = 16, S_ = 4096, D_ = 512, M_ = 2048;
constexpr int NROWS = B_ * S_;   // 65536
constexpr int NC    = 3 * D_;    // 1536

// ---------------------------------------------------------------------------
// Scratch (device globals: no allocations allowed)
// ---------------------------------------------------------------------------
__device__ float g_v[(size_t)NROWS * D_];          // v projection
__device__ __half g_xh[(size_t)NROWS * D_];        // x hi split (fp16)
__device__ __half g_xl[(size_t)NROWS * D_];        // x lo split
__device__ __half g_wh[(size_t)NC * D_];           // W^T hi  [n][k]
__device__ __half g_wl[(size_t)NC * D_];           // W^T lo  [n][k]
__device__ float g_scores[NROWS];
__device__ float g_attn[NROWS];
__device__ float g_part[B_ * 32 * D_];
__device__ float g_h[B_ * D_];
__device__ float g_h1[B_ * M_];
__device__ float g_h2[B_ * M_];

// ---------------------------------------------------------------------------
// Helpers (baseline PTX: ldmatrix / mma.sync / cp.async — sm_80+)
// ---------------------------------------------------------------------------
__device__ __forceinline__ uint32_t smem_u32(const void* p) {
    uint32_t a;
    asm("{ .reg .u64 t; cvta.to.shared.u64 t, %1; cvt.u32.u64 %0, t; }"
        : "=r"(a) : "l"(p));
    return a;
}

// Swizzle<2,4,3> for 64-byte rows: bits[5:4] ^= bits[8:7]
#define SWZ64(o) ((o) ^ ((((uint32_t)(o)) >> 3) & 0x30u))

__device__ __forceinline__ void cp_async16(uint32_t sdst, const void* gsrc) {
    asm volatile("cp.async.cg.shared.global [%0], [%1], 16;"
                 :: "r"(sdst), "l"(gsrc) : "memory");
}
#define CP_COMMIT() asm volatile("cp.async.commit_group;" ::: "memory")
#define CP_WAIT(n)  asm volatile("cp.async.wait_group %0;" :: "n"(n) : "memory")

__device__ __forceinline__ void ldm_x4(uint32_t* r, uint32_t addr) {
    asm volatile("ldmatrix.sync.aligned.m8n8.x4.shared.b16 {%0,%1,%2,%3}, [%4];"
                 : "=r"(r[0]), "=r"(r[1]), "=r"(r[2]), "=r"(r[3]) : "r"(addr));
}

// fp16 inputs, fp32 accumulators
__device__ __forceinline__ void mma_f32acc(float* c, const uint32_t* a, const uint32_t* b) {
    asm volatile(
        "mma.sync.aligned.m16n8k16.row.col.f32.f16.f16.f32 "
        "{%0,%1,%2,%3}, {%4,%5,%6,%7}, {%8,%9}, {%0,%1,%2,%3};"
        : "+f"(c[0]), "+f"(c[1]), "+f"(c[2]), "+f"(c[3])
        : "r"(a[0]), "r"(a[1]), "r"(a[2]), "r"(a[3]), "r"(b[0]), "r"(b[1]));
}

// fp16 inputs, fp16 accumulators (2 packed regs)
__device__ __forceinline__ void mma_f16acc(uint32_t* c, const uint32_t* a, const uint32_t* b) {
    asm volatile(
        "mma.sync.aligned.m16n8k16.row.col.f16.f16.f16.f16 "
        "{%0,%1}, {%2,%3,%4,%5}, {%6,%7}, {%0,%1};"
        : "+r"(c[0]), "+r"(c[1])
        : "r"(a[0]), "r"(a[1]), "r"(a[2]), "r"(a[3]), "r"(b[0]), "r"(b[1]));
}

// ---------------------------------------------------------------------------
// fp32 -> fp16 hi/lo split conversions
// ---------------------------------------------------------------------------
__global__ void convert_x(const float* __restrict__ x)
{
    const size_t i = (size_t)blockIdx.x * blockDim.x + threadIdx.x;  // float4 idx
    const float4 v = ((const float4*)x)[i];
    __half h0 = __float2half_rn(v.x), h1 = __float2half_rn(v.y);
    __half h2 = __float2half_rn(v.z), h3 = __float2half_rn(v.w);
    __half l0 = __float2half_rn(v.x - __half2float(h0));
    __half l1 = __float2half_rn(v.y - __half2float(h1));
    __half l2 = __float2half_rn(v.z - __half2float(h2));
    __half l3 = __float2half_rn(v.w - __half2float(h3));
    ((__half2*)g_xh)[i * 2 + 0] = __halves2half2(h0, h1);
    ((__half2*)g_xh)[i * 2 + 1] = __halves2half2(h2, h3);
    ((__half2*)g_xl)[i * 2 + 0] = __halves2half2(l0, l1);
    ((__half2*)g_xl)[i * 2 + 1] = __halves2half2(l2, l3);
}

__global__ void convert_w(const float* __restrict__ W)
{
    const int e = blockIdx.x * blockDim.x + threadIdx.x;   // < 512*1536
    const int k = e / NC, n = e % NC;
    const float v = W[e];
    __half hi = __float2half_rn(v);
    __half lo = __float2half_rn(v - __half2float(hi));
    g_wh[(size_t)n * D_ + k] = hi;
    g_wl[(size_t)n * D_ + k] = lo;
}

// ---------------------------------------------------------------------------
// QKV GEMM via mma.sync fp16x3 (hi*hi in fp32 acc; hi*lo + lo*hi in fp16 acc):
//   C[65536 x 1536] = x[65536 x 512] @ W[512 x 1536] + b
// CTA tile 128x128, K-chunk 32, 3-stage cp.async pipeline (96KB dynamic smem).
// ---------------------------------------------------------------------------
constexpr int TM = 128, TN = 128, TK = 32;
constexpr int NCHUNK = D_ / TK;  // 16
// stage: Ah, Al, Bh, Bl each 128 rows x 64B = 8KB
constexpr int TILE_BYTES  = 128 * 64;
constexpr int STAGE_BYTES = 4 * TILE_BYTES;            // 32 KB
constexpr int QKV_SMEM    = 3 * STAGE_BYTES;           // 96 KB dynamic

__global__ __launch_bounds__(256)
void qkv_mma(const float* __restrict__ bias,
             float* __restrict__ q_out, float* __restrict__ k_out)
{
    extern __shared__ __align__(128) uint8_t sm[];
    const uint32_t sb = smem_u32(sm);

    const int tid  = threadIdx.x;
    const int warp = tid >> 5, lane = tid & 31;
    const int n0 = blockIdx.x * TN;
    const int m0 = blockIdx.y * TM;
    const int wm = (warp & 1) * 64;        // warp row offset
    const int wn = (warp >> 1) * 32;       // warp col offset

    // cp.async coords: per tile, 2 chunks of 16B per thread (512 chunks/tile)
    const int r0l = tid >> 2;              // rows 0..63   (j=0)
    const int c0l = tid & 3;               // 16B col 0..3
    const uint32_t so0 = SWZ64(r0l * 64 + c0l * 16);
    const uint32_t so1 = SWZ64((r0l + 64) * 64 + c0l * 16);

    auto load_stage = [&](int stage, int ch) {
        const uint32_t s0 = sb + stage * STAGE_BYTES;
        const int kcol = ch * TK + c0l * 8;
        const size_t ga0 = (size_t)(m0 + r0l) * D_ + kcol;
        const size_t ga1 = (size_t)(m0 + r0l + 64) * D_ + kcol;
        const size_t gb0 = (size_t)(n0 + r0l) * D_ + kcol;
        const size_t gb1 = (size_t)(n0 + r0l + 64) * D_ + kcol;
        cp_async16(s0 + 0 * TILE_BYTES + so0, g_xh + ga0);
        cp_async16(s0 + 0 * TILE_BYTES + so1, g_xh + ga1);
        cp_async16(s0 + 1 * TILE_BYTES + so0, g_xl + ga0);
        cp_async16(s0 + 1 * TILE_BYTES + so1, g_xl + ga1);
        cp_async16(s0 + 2 * TILE_BYTES + so0, g_wh + gb0);
        cp_async16(s0 + 2 * TILE_BYTES + so1, g_wh + gb1);
        cp_async16(s0 + 3 * TILE_BYTES + so0, g_wl + gb0);
        cp_async16(s0 + 3 * TILE_BYTES + so1, g_wl + gb1);
    };

    float acc[4][4][4];
    uint32_t accl[4][4][2];
    #pragma unroll
    for (int i = 0; i < 4; i++)
        #pragma unroll
        for (int j = 0; j < 4; j++) {
            #pragma unroll
            for (int e = 0; e < 4; e++) acc[i][j][e] = 0.f;
            accl[i][j][0] = 0u; accl[i][j][1] = 0u;
        }

    // ldmatrix lane addressing components
    const uint32_t a_row = (lane & 15);                       // + wm + mf*16
    const uint32_t a_byt = (lane >> 4) << 4;                  // + kk*32
    const uint32_t b_row = ((lane >> 4) << 3) + (lane & 7);   // + wn + p*16
    const uint32_t b_byt = ((lane >> 3) & 1) << 4;            // + kk*32

    load_stage(0, 0); CP_COMMIT();
    load_stage(1, 1); CP_COMMIT();

    for (int ch = 0; ch < NCHUNK; ch++) {
        if (ch + 2 < NCHUNK) {
            load_stage((ch + 2) % 3, ch + 2); CP_COMMIT();
            CP_WAIT(2);
        } else {
            CP_WAIT(0);
        }
        __syncthreads();

        const uint32_t s0 = sb + (ch % 3) * STAGE_BYTES;

        #pragma unroll
        for (int kk = 0; kk < 2; kk++) {
            uint32_t ra[4], rb[2];
            #pragma unroll
            for (int mf = 0; mf < 4; mf++)
                ra[mf] = SWZ64((uint32_t)(wm + mf * 16 + a_row) * 64 + kk * 32 + a_byt);
            #pragma unroll
            for (int p = 0; p < 2; p++)
                rb[p] = SWZ64((uint32_t)(wn + p * 16 + b_row) * 64 + kk * 32 + b_byt);

            // --- pass 1: Ah x Bh -> fp32 acc ---
            uint32_t ah[4][4];
            #pragma unroll
            for (int mf = 0; mf < 4; mf++) ldm_x4(ah[mf], s0 + 0 * TILE_BYTES + ra[mf]);
            uint32_t bh[4][2];
            #pragma unroll
            for (int p = 0; p < 2; p++) {
                uint32_t t[4];
                ldm_x4(t, s0 + 2 * TILE_BYTES + rb[p]);
                bh[p * 2][0] = t[0]; bh[p * 2][1] = t[1];
                bh[p * 2 + 1][0] = t[2]; bh[p * 2 + 1][1] = t[3];
            }
            #pragma unroll
            for (int mf = 0; mf < 4; mf++)
                #pragma unroll
                for (int nf = 0; nf < 4; nf++) mma_f32acc(acc[mf][nf], ah[mf], bh[nf]);

            // --- pass 2: Ah x Bl -> fp16 acc ---
            {
                uint32_t bl[4][2];
                #pragma unroll
                for (int p = 0; p < 2; p++) {
                    uint32_t t[4];
                    ldm_x4(t, s0 + 3 * TILE_BYTES + rb[p]);
                    bl[p * 2][0] = t[0]; bl[p * 2][1] = t[1];
                    bl[p * 2 + 1][0] = t[2]; bl[p * 2 + 1][1] = t[3];
                }
                #pragma unroll
                for (int mf = 0; mf < 4; mf++)
                    #pragma unroll
                    for (int nf = 0; nf < 4; nf++) mma_f16acc(accl[mf][nf], ah[mf], bl[nf]);
            }

            // --- pass 3: Al x Bh -> fp16 acc (bh reused; ah dead) ---
            {
                uint32_t al[4][4];
                #pragma unroll
                for (int mf = 0; mf < 4; mf++) ldm_x4(al[mf], s0 + 1 * TILE_BYTES + ra[mf]);
                #pragma unroll
                for (int mf = 0; mf < 4; mf++)
                    #pragma unroll
                    for (int nf = 0; nf < 4; nf++) mma_f16acc(accl[mf][nf], al[mf], bh[nf]);
            }
        }
        __syncthreads();
    }

    // Epilogue: fp32 acc + fp16 lo acc + bias -> float2 global stores
    const int region = n0 >> 9;                 // 0=q, 1=k, 2=v
    float* dst = (region == 0) ? q_out : (region == 1 ? k_out : (float*)g_v);
    const int cbase = n0 - region * 512;

    #pragma unroll
    for (int mf = 0; mf < 4; mf++) {
        #pragma unroll
        for (int nf = 0; nf < 4; nf++) {
            const int colg = n0 + wn + nf * 8 + (lane & 3) * 2;
            const float2 bv = *(const float2*)(bias + colg);
            const int col = cbase + wn + nf * 8 + (lane & 3) * 2;
            const int r0 = m0 + wm + mf * 16 + (lane >> 2);
            const float2 l01 = __half22float2(*(const __half2*)&accl[mf][nf][0]);
            const float2 l23 = __half22float2(*(const __half2*)&accl[mf][nf][1]);
            float2 v0 = make_float2(acc[mf][nf][0] + l01.x + bv.x,
                                    acc[mf][nf][1] + l01.y + bv.y);
            float2 v1 = make_float2(acc[mf][nf][2] + l23.x + bv.x,
                                    acc[mf][nf][3] + l23.y + bv.y);
            *(float2*)(dst + (size_t)r0 * D_ + col)       = v0;
            *(float2*)(dst + (size_t)(r0 + 8) * D_ + col) = v1;
        }
    }
}

// ---------------------------------------------------------------------------
// scores[b,s] = q_last[b,:] . k[b,s,:]    (one warp per (b,s))
// ---------------------------------------------------------------------------
__global__ void scores_kernel(const float* __restrict__ q, const float* __restrict__ k)
{
    const int gw   = (blockIdx.x * blockDim.x + threadIdx.x) >> 5;
    const int lane = threadIdx.x & 31;
    const int b    = gw >> 12;

    const float4* qr = (const float4*)(q + ((size_t)b * S_ + (S_ - 1)) * D_);
    const float4* kr = (const float4*)(k + (size_t)gw * D_);

    float acc = 0.f;
    #pragma unroll
    for (int it = 0; it < 4; it++) {
        float4 qv = qr[lane + it * 32];
        float4 kv = kr[lane + it * 32];
        acc += qv.x * kv.x + qv.y * kv.y + qv.z * kv.z + qv.w * kv.w;
    }
    #pragma unroll
    for (int off = 16; off; off >>= 1) acc += __shfl_xor_sync(0xffffffffu, acc, off);
    if (lane == 0) g_scores[gw] = acc;
}

__global__ void softmax_kernel()
{
    __shared__ float red[512];
    const int b = blockIdx.x, tid = threadIdx.x;
    const float* sc = g_scores + (size_t)b * S_;

    float lm = -1e30f;
    for (int i = tid; i < S_; i += 512) lm = fmaxf(lm, sc[i]);
    red[tid] = lm; __syncthreads();
    for (int s = 256; s; s >>= 1) {
        if (tid < s) red[tid] = fmaxf(red[tid], red[tid + s]);
        __syncthreads();
    }
    const float mx = red[0];
    __syncthreads();

    float ls = 0.f;
    for (int i = tid; i < S_; i += 512) {
        float e = expf(sc[i] - mx);
        g_attn[(size_t)b * S_ + i] = e;
        ls += e;
    }
    red[tid] = ls; __syncthreads();
    for (int s = 256; s; s >>= 1) {
        if (tid < s) red[tid] += red[tid + s];
        __syncthreads();
    }
    const float inv = 1.f / red[0];
    for (int i = tid; i < S_; i += 512) g_attn[(size_t)b * S_ + i] *= inv;
}

// ---------------------------------------------------------------------------
// sa_last partials: block (b, chunk) accumulates 128 s-rows of attn*v
// ---------------------------------------------------------------------------
__global__ void sa_part_kernel()
{
    const int b = blockIdx.x, ch = blockIdx.y, d = threadIdx.x;
    const float* vp = g_v + ((size_t)b * S_ + ch * 128) * D_ + d;
    const float* ap = g_attn + (size_t)b * S_ + ch * 128;
    float a0 = 0.f, a1 = 0.f;
    #pragma unroll 8
    for (int s = 0; s < 128; s += 2) {
        a0 = fmaf(ap[s],     vp[(size_t)s * D_],        a0);
        a1 = fmaf(ap[s + 1], vp[(size_t)(s + 1) * D_],  a1);
    }
    g_part[(b * 32 + ch) * D_ + d] = a0 + a1;
}

__global__ void sa_reduce_kernel(const float* __restrict__ x)
{
    const int b = blockIdx.x, d = threadIdx.x;
    float acc = x[((size_t)b * S_ + (S_ - 1)) * D_ + d];
    #pragma unroll
    for (int ch = 0; ch < 32; ch++) acc += g_part[(b * 32 + ch) * D_ + d];
    g_h[b * D_ + d] = acc;
}

__global__ __launch_bounds__(256)
void mlp1_kernel(const float* __restrict__ W1, const float* __restrict__ b1)
{
    __shared__ float hs[D_];
    const int b = blockIdx.x, tid = threadIdx.x;
    hs[tid]       = g_h[b * D_ + tid];
    hs[tid + 256] = g_h[b * D_ + tid + 256];
    __syncthreads();
    const int m = blockIdx.y * 256 + tid;
    float acc = b1[m];
    #pragma unroll 8
    for (int k = 0; k < D_; k++) acc = fmaf(hs[k], W1[(size_t)k * M_ + m], acc);
    g_h1[b * M_ + m] = fmaxf(acc, 0.f);
}

__global__ __launch_bounds__(256)
void mlp2_kernel(const float* __restrict__ W2, const float* __restrict__ b2)
{
    __shared__ float hs[M_];
    const int b = blockIdx.x, tid = threadIdx.x;
    for (int i = tid; i < M_; i += 256) hs[i] = g_h1[b * M_ + i];
    __syncthreads();
    const int m = blockIdx.y * 256 + tid;
    float acc = b2[m];
    #pragma unroll 8
    for (int k = 0; k < M_; k++) acc = fmaf(hs[k], W2[(size_t)k * M_ + m], acc);
    g_h2[b * M_ + m] = fmaxf(acc, 0.f);
}

__global__ void mlp3_kernel(const float* __restrict__ W3, const float* __restrict__ b3,
                            float* __restrict__ out)
{
    const int w = threadIdx.x >> 5, lane = threadIdx.x & 31;
    float acc = 0.f;
    #pragma unroll
    for (int i = 0; i < M_ / 32; i++)
        acc = fmaf(g_h2[w * M_ + lane + i * 32], W3[lane + i * 32], acc);
    #pragma unroll
    for (int off = 16; off; off >>= 1) acc += __shfl_xor_sync(0xffffffffu, acc, off);
    if (lane == 0) out[w] = acc + b3[0];
}

// ---------------------------------------------------------------------------
// Entry. Output layout: (out, q, k) flat: [0,16) out, then q, then k.
// ---------------------------------------------------------------------------
extern "C" void kernel_launch(void* const* d_in, const int* in_sizes, int n_in,
                              void* d_out, int out_size)
{
    const float* x     = (const float*)d_in[0];
    const float* W_qkv = (const float*)d_in[1];
    const float* b_qkv = (const float*)d_in[2];
    const float* W1    = (const float*)d_in[3];
    const float* b1    = (const float*)d_in[4];
    const float* W2    = (const float*)d_in[5];
    const float* b2    = (const float*)d_in[6];
    const float* W3    = (const float*)d_in[7];
    const float* b3    = (const float*)d_in[8];

    float* out   = (float*)d_out;
    float* q_out = out + 16;
    float* k_out = out + 16 + (size_t)NROWS * D_;

    // Unconditional (no static guards): host-side attribute set, not a stream op.
    cudaFuncSetAttribute(qkv_mma, cudaFuncAttributeMaxDynamicSharedMemorySize, QKV_SMEM);

    convert_x<<<(NROWS * D_ / 4) / 256, 256>>>(x);
    convert_w<<<(D_ * NC) / 256, 256>>>(W_qkv);
    qkv_mma<<<dim3(NC / TN, NROWS / TM), 256, QKV_SMEM>>>(b_qkv, q_out, k_out);
    scores_kernel<<<NROWS / 8, 256>>>(q_out, k_out);
    softmax_kernel<<<B_, 512>>>();
    sa_part_kernel<<<dim3(B_, 32), 512>>>();
    sa_reduce_kernel<<<B_, D_>>>(x);
    mlp1_kernel<<<dim3(B_, M_ / 256), 256>>>(W1, b1);
    mlp2_kernel<<<dim3(B_, M_ / 256), 256>>>(W2, b2);
    mlp3_kernel<<<1, 512>>>(W3, b3, out);
}

// round 6
// speedup vs baseline: 1.0999x; 1.0999x over previous
#include <cuda_runtime.h>
#include <cuda_fp16.h>
#include <cstdint>

// Problem dims
constexpr int B_ = 16, S_ = 4096, D_ = 512, M_ = 2048;
constexpr int NROWS = B_ * S_;   // 65536
constexpr int NC    = 3 * D_;    // 1536

// ---------------------------------------------------------------------------
// Scratch (device globals: no allocations allowed)
// ---------------------------------------------------------------------------
__device__ float g_v[(size_t)NROWS * D_];          // v projection
__device__ __half g_xh[(size_t)NROWS * D_];        // x hi split (fp16)
__device__ __half g_xl[(size_t)NROWS * D_];        // x lo split
__device__ __half g_wh[(size_t)NC * D_];           // W^T hi  [n][k]
__device__ __half g_wl[(size_t)NC * D_];           // W^T lo  [n][k]
__device__ float g_scores[NROWS];
__device__ float g_attn[NROWS];
__device__ float g_part[B_ * 32 * D_];
__device__ float g_h[B_ * D_];
__device__ float g_h1[B_ * M_];
__device__ float g_h2[B_ * M_];

// ---------------------------------------------------------------------------
// Helpers (baseline PTX: ldmatrix / mma.sync / cp.async — sm_80+)
// ---------------------------------------------------------------------------
__device__ __forceinline__ uint32_t smem_u32(const void* p) {
    uint32_t a;
    asm("{ .reg .u64 t; cvta.to.shared.u64 t, %1; cvt.u32.u64 %0, t; }"
        : "=r"(a) : "l"(p));
    return a;
}

// Swizzle<2,4,3> for 64-byte rows: bits[5:4] ^= bits[8:7]
#define SWZ64(o) ((o) ^ ((((uint32_t)(o)) >> 3) & 0x30u))

__device__ __forceinline__ void cp_async16(uint32_t sdst, const void* gsrc) {
    asm volatile("cp.async.cg.shared.global [%0], [%1], 16;"
                 :: "r"(sdst), "l"(gsrc) : "memory");
}
#define CP_COMMIT() asm volatile("cp.async.commit_group;" ::: "memory")
#define CP_WAIT(n)  asm volatile("cp.async.wait_group %0;" :: "n"(n) : "memory")

__device__ __forceinline__ void ldm_x4(uint32_t* r, uint32_t addr) {
    asm volatile("ldmatrix.sync.aligned.m8n8.x4.shared.b16 {%0,%1,%2,%3}, [%4];"
                 : "=r"(r[0]), "=r"(r[1]), "=r"(r[2]), "=r"(r[3]) : "r"(addr));
}

// fp16 inputs, fp32 accumulators
__device__ __forceinline__ void mma_f32acc(float* c, const uint32_t* a, const uint32_t* b) {
    asm volatile(
        "mma.sync.aligned.m16n8k16.row.col.f32.f16.f16.f32 "
        "{%0,%1,%2,%3}, {%4,%5,%6,%7}, {%8,%9}, {%0,%1,%2,%3};"
        : "+f"(c[0]), "+f"(c[1]), "+f"(c[2]), "+f"(c[3])
        : "r"(a[0]), "r"(a[1]), "r"(a[2]), "r"(a[3]), "r"(b[0]), "r"(b[1]));
}

// fp16 inputs, fp16 accumulators (2 packed regs)
__device__ __forceinline__ void mma_f16acc(uint32_t* c, const uint32_t* a, const uint32_t* b) {
    asm volatile(
        "mma.sync.aligned.m16n8k16.row.col.f16.f16.f16.f16 "
        "{%0,%1}, {%2,%3,%4,%5}, {%6,%7}, {%0,%1};"
        : "+r"(c[0]), "+r"(c[1])
        : "r"(a[0]), "r"(a[1]), "r"(a[2]), "r"(a[3]), "r"(b[0]), "r"(b[1]));
}

// ---------------------------------------------------------------------------
// fp32 -> fp16 hi/lo split conversions
// ---------------------------------------------------------------------------
__global__ void convert_x(const float* __restrict__ x)
{
    const size_t i = (size_t)blockIdx.x * blockDim.x + threadIdx.x;  // float4 idx
    const float4 v = ((const float4*)x)[i];
    __half h0 = __float2half_rn(v.x), h1 = __float2half_rn(v.y);
    __half h2 = __float2half_rn(v.z), h3 = __float2half_rn(v.w);
    __half l0 = __float2half_rn(v.x - __half2float(h0));
    __half l1 = __float2half_rn(v.y - __half2float(h1));
    __half l2 = __float2half_rn(v.z - __half2float(h2));
    __half l3 = __float2half_rn(v.w - __half2float(h3));
    ((__half2*)g_xh)[i * 2 + 0] = __halves2half2(h0, h1);
    ((__half2*)g_xh)[i * 2 + 1] = __halves2half2(h2, h3);
    ((__half2*)g_xl)[i * 2 + 0] = __halves2half2(l0, l1);
    ((__half2*)g_xl)[i * 2 + 1] = __halves2half2(l2, l3);
}

__global__ void convert_w(const float* __restrict__ W)
{
    const int e = blockIdx.x * blockDim.x + threadIdx.x;   // < 512*1536
    const int k = e / NC, n = e % NC;
    const float v = W[e];
    __half hi = __float2half_rn(v);
    __half lo = __float2half_rn(v - __half2float(hi));
    g_wh[(size_t)n * D_ + k] = hi;
    g_wl[(size_t)n * D_ + k] = lo;
}

// ---------------------------------------------------------------------------
// QKV GEMM via mma.sync fp16x3 (hi*hi fp32 acc; cross terms fp16 acc):
//   C[65536 x 1536] = x[65536 x 512] @ W[512 x 1536] + b
// CTA tile 128x64, warp tile 32x32 (8 warps, 4x2), K-chunk 32,
// 3-stage cp.async pipeline, 72KB dynamic smem, 2 CTAs/SM.
// ---------------------------------------------------------------------------
constexpr int TM = 128, TN = 64, TK = 32;
constexpr int NCHUNK = D_ / TK;  // 16
constexpr int A_TILE = 128 * 64;                       // 8 KB
constexpr int B_TILE = 64 * 64;                        // 4 KB
constexpr int OFF_AH = 0;
constexpr int OFF_AL = OFF_AH + A_TILE;
constexpr int OFF_BH = OFF_AL + A_TILE;
constexpr int OFF_BL = OFF_BH + B_TILE;
constexpr int STAGE_BYTES = OFF_BL + B_TILE;           // 24 KB
constexpr int QKV_SMEM    = 3 * STAGE_BYTES;           // 72 KB dynamic

__global__ __launch_bounds__(256, 2)
void qkv_mma(const float* __restrict__ bias,
             float* __restrict__ q_out, float* __restrict__ k_out)
{
    extern __shared__ __align__(128) uint8_t sm[];
    const uint32_t sb = smem_u32(sm);

    const int tid  = threadIdx.x;
    const int warp = tid >> 5, lane = tid & 31;
    const int n0 = blockIdx.x * TN;
    const int m0 = blockIdx.y * TM;
    const int wm = (warp >> 1) * 32;       // warp row offset (0..96)
    const int wn = (warp & 1) * 32;        // warp col offset (0 or 32)

    // cp.async coords: 64-row x 4-chunk pattern per slab
    const int rl = tid >> 2;               // rows 0..63
    const int cl = tid & 3;                // 16B col 0..3
    const uint32_t soA0 = SWZ64(rl * 64 + cl * 16);
    const uint32_t soA1 = SWZ64((rl + 64) * 64 + cl * 16);
    const uint32_t soB  = soA0;

    auto load_stage = [&](int stage, int ch) {
        const uint32_t s0 = sb + stage * STAGE_BYTES;
        const int kcol = ch * TK + cl * 8;
        const size_t ga0 = (size_t)(m0 + rl) * D_ + kcol;
        const size_t ga1 = (size_t)(m0 + rl + 64) * D_ + kcol;
        const size_t gb  = (size_t)(n0 + rl) * D_ + kcol;
        cp_async16(s0 + OFF_AH + soA0, g_xh + ga0);
        cp_async16(s0 + OFF_AH + soA1, g_xh + ga1);
        cp_async16(s0 + OFF_AL + soA0, g_xl + ga0);
        cp_async16(s0 + OFF_AL + soA1, g_xl + ga1);
        cp_async16(s0 + OFF_BH + soB,  g_wh + gb);
        cp_async16(s0 + OFF_BL + soB,  g_wl + gb);
    };

    float acc[2][4][4];
    uint32_t accl[2][4][2];
    #pragma unroll
    for (int i = 0; i < 2; i++)
        #pragma unroll
        for (int j = 0; j < 4; j++) {
            #pragma unroll
            for (int e = 0; e < 4; e++) acc[i][j][e] = 0.f;
            accl[i][j][0] = 0u; accl[i][j][1] = 0u;
        }

    // ldmatrix lane addressing components
    const uint32_t a_row = (lane & 15);                       // + wm + mf*16
    const uint32_t a_byt = (lane >> 4) << 4;                  // + kk*32
    const uint32_t b_row = ((lane >> 4) << 3) + (lane & 7);   // + wn + p*16
    const uint32_t b_byt = ((lane >> 3) & 1) << 4;            // + kk*32

    load_stage(0, 0); CP_COMMIT();
    load_stage(1, 1); CP_COMMIT();

    for (int ch = 0; ch < NCHUNK; ch++) {
        if (ch + 2 < NCHUNK) {
            load_stage((ch + 2) % 3, ch + 2); CP_COMMIT();
            CP_WAIT(2);
        } else {
            CP_WAIT(0);
        }
        __syncthreads();

        const uint32_t s0 = sb + (ch % 3) * STAGE_BYTES;

        #pragma unroll
        for (int kk = 0; kk < 2; kk++) {
            uint32_t ra[2], rb[2];
            #pragma unroll
            for (int mf = 0; mf < 2; mf++)
                ra[mf] = SWZ64((uint32_t)(wm + mf * 16 + a_row) * 64 + kk * 32 + a_byt);
            #pragma unroll
            for (int p = 0; p < 2; p++)
                rb[p] = SWZ64((uint32_t)(wn + p * 16 + b_row) * 64 + kk * 32 + b_byt);

            // --- pass 1: Ah x Bh -> fp32 acc ---
            uint32_t ah[2][4];
            #pragma unroll
            for (int mf = 0; mf < 2; mf++) ldm_x4(ah[mf], s0 + OFF_AH + ra[mf]);
            uint32_t bh[4][2];
            #pragma unroll
            for (int p = 0; p < 2; p++) {
                uint32_t t[4];
                ldm_x4(t, s0 + OFF_BH + rb[p]);
                bh[p * 2][0] = t[0]; bh[p * 2][1] = t[1];
                bh[p * 2 + 1][0] = t[2]; bh[p * 2 + 1][1] = t[3];
            }
            #pragma unroll
            for (int mf = 0; mf < 2; mf++)
                #pragma unroll
                for (int nf = 0; nf < 4; nf++) mma_f32acc(acc[mf][nf], ah[mf], bh[nf]);

            // --- pass 2: Ah x Bl -> fp16 acc ---
            {
                uint32_t bl[4][2];
                #pragma unroll
                for (int p = 0; p < 2; p++) {
                    uint32_t t[4];
                    ldm_x4(t, s0 + OFF_BL + rb[p]);
                    bl[p * 2][0] = t[0]; bl[p * 2][1] = t[1];
                    bl[p * 2 + 1][0] = t[2]; bl[p * 2 + 1][1] = t[3];
                }
                #pragma unroll
                for (int mf = 0; mf < 2; mf++)
                    #pragma unroll
                    for (int nf = 0; nf < 4; nf++) mma_f16acc(accl[mf][nf], ah[mf], bl[nf]);
            }

            // --- pass 3: Al x Bh -> fp16 acc (bh reused; ah dead) ---
            {
                uint32_t al[2][4];
                #pragma unroll
                for (int mf = 0; mf < 2; mf++) ldm_x4(al[mf], s0 + OFF_AL + ra[mf]);
                #pragma unroll
                for (int mf = 0; mf < 2; mf++)
                    #pragma unroll
                    for (int nf = 0; nf < 4; nf++) mma_f16acc(accl[mf][nf], al[mf], bh[nf]);
            }
        }
        __syncthreads();
    }

    // Epilogue: fp32 acc + fp16 lo acc + bias -> float2 global stores
    const int region = n0 >> 9;                 // 0=q, 1=k, 2=v
    float* dst = (region == 0) ? q_out : (region == 1 ? k_out : (float*)g_v);
    const int cbase = n0 - region * 512;

    #pragma unroll
    for (int mf = 0; mf < 2; mf++) {
        #pragma unroll
        for (int nf = 0; nf < 4; nf++) {
            const int colg = n0 + wn + nf * 8 + (lane & 3) * 2;
            const float2 bv = *(const float2*)(bias + colg);
            const int col = cbase + wn + nf * 8 + (lane & 3) * 2;
            const int r0 = m0 + wm + mf * 16 + (lane >> 2);
            const float2 l01 = __half22float2(*(const __half2*)&accl[mf][nf][0]);
            const float2 l23 = __half22float2(*(const __half2*)&accl[mf][nf][1]);
            float2 v0 = make_float2(acc[mf][nf][0] + l01.x + bv.x,
                                    acc[mf][nf][1] + l01.y + bv.y);
            float2 v1 = make_float2(acc[mf][nf][2] + l23.x + bv.x,
                                    acc[mf][nf][3] + l23.y + bv.y);
            *(float2*)(dst + (size_t)r0 * D_ + col)       = v0;
            *(float2*)(dst + (size_t)(r0 + 8) * D_ + col) = v1;
        }
    }
}

// ---------------------------------------------------------------------------
// scores[b,s] = q_last[b,:] . k[b,s,:]    (one warp per (b,s))
// ---------------------------------------------------------------------------
__global__ void scores_kernel(const float* __restrict__ q, const float* __restrict__ k)
{
    const int gw   = (blockIdx.x * blockDim.x + threadIdx.x) >> 5;
    const int lane = threadIdx.x & 31;
    const int b    = gw >> 12;

    const float4* qr = (const float4*)(q + ((size_t)b * S_ + (S_ - 1)) * D_);
    const float4* kr = (const float4*)(k + (size_t)gw * D_);

    float acc = 0.f;
    #pragma unroll
    for (int it = 0; it < 4; it++) {
        float4 qv = qr[lane + it * 32];
        float4 kv = kr[lane + it * 32];
        acc += qv.x * kv.x + qv.y * kv.y + qv.z * kv.z + qv.w * kv.w;
    }
    #pragma unroll
    for (int off = 16; off; off >>= 1) acc += __shfl_xor_sync(0xffffffffu, acc, off);
    if (lane == 0) g_scores[gw] = acc;
}

__global__ void softmax_kernel()
{
    __shared__ float red[512];
    const int b = blockIdx.x, tid = threadIdx.x;
    const float* sc = g_scores + (size_t)b * S_;

    float lm = -1e30f;
    for (int i = tid; i < S_; i += 512) lm = fmaxf(lm, sc[i]);
    red[tid] = lm; __syncthreads();
    for (int s = 256; s; s >>= 1) {
        if (tid < s) red[tid] = fmaxf(red[tid], red[tid + s]);
        __syncthreads();
    }
    const float mx = red[0];
    __syncthreads();

    float ls = 0.f;
    for (int i = tid; i < S_; i += 512) {
        float e = expf(sc[i] - mx);
        g_attn[(size_t)b * S_ + i] = e;
        ls += e;
    }
    red[tid] = ls; __syncthreads();
    for (int s = 256; s; s >>= 1) {
        if (tid < s) red[tid] += red[tid + s];
        __syncthreads();
    }
    const float inv = 1.f / red[0];
    for (int i = tid; i < S_; i += 512) g_attn[(size_t)b * S_ + i] *= inv;
}

// ---------------------------------------------------------------------------
// sa_last partials: block (b, chunk) accumulates 128 s-rows of attn*v
// ---------------------------------------------------------------------------
__global__ void sa_part_kernel()
{
    const int b = blockIdx.x, ch = blockIdx.y, d = threadIdx.x;
    const float* vp = g_v + ((size_t)b * S_ + ch * 128) * D_ + d;
    const float* ap = g_attn + (size_t)b * S_ + ch * 128;
    float a0 = 0.f, a1 = 0.f;
    #pragma unroll 8
    for (int s = 0; s < 128; s += 2) {
        a0 = fmaf(ap[s],     vp[(size_t)s * D_],        a0);
        a1 = fmaf(ap[s + 1], vp[(size_t)(s + 1) * D_],  a1);
    }
    g_part[(b * 32 + ch) * D_ + d] = a0 + a1;
}

__global__ void sa_reduce_kernel(const float* __restrict__ x)
{
    const int b = blockIdx.x, d = threadIdx.x;
    float acc = x[((size_t)b * S_ + (S_ - 1)) * D_ + d];
    #pragma unroll
    for (int ch = 0; ch < 32; ch++) acc += g_part[(b * 32 + ch) * D_ + d];
    g_h[b * D_ + d] = acc;
}

__global__ __launch_bounds__(256)
void mlp1_kernel(const float* __restrict__ W1, const float* __restrict__ b1)
{
    __shared__ float hs[D_];
    const int b = blockIdx.x, tid = threadIdx.x;
    hs[tid]       = g_h[b * D_ + tid];
    hs[tid + 256] = g_h[b * D_ + tid + 256];
    __syncthreads();
    const int m = blockIdx.y * 256 + tid;
    float acc = b1[m];
    #pragma unroll 8
    for (int k = 0; k < D_; k++) acc = fmaf(hs[k], W1[(size_t)k * M_ + m], acc);
    g_h1[b * M_ + m] = fmaxf(acc, 0.f);
}

__global__ __launch_bounds__(256)
void mlp2_kernel(const float* __restrict__ W2, const float* __restrict__ b2)
{
    __shared__ float hs[M_];
    const int b = blockIdx.x, tid = threadIdx.x;
    for (int i = tid; i < M_; i += 256) hs[i] = g_h1[b * M_ + i];
    __syncthreads();
    const int m = blockIdx.y * 256 + tid;
    float acc = b2[m];
    #pragma unroll 8
    for (int k = 0; k < M_; k++) acc = fmaf(hs[k], W2[(size_t)k * M_ + m], acc);
    g_h2[b * M_ + m] = fmaxf(acc, 0.f);
}

__global__ void mlp3_kernel(const float* __restrict__ W3, const float* __restrict__ b3,
                            float* __restrict__ out)
{
    const int w = threadIdx.x >> 5, lane = threadIdx.x & 31;
    float acc = 0.f;
    #pragma unroll
    for (int i = 0; i < M_ / 32; i++)
        acc = fmaf(g_h2[w * M_ + lane + i * 32], W3[lane + i * 32], acc);
    #pragma unroll
    for (int off = 16; off; off >>= 1) acc += __shfl_xor_sync(0xffffffffu, acc, off);
    if (lane == 0) out[w] = acc + b3[0];
}

// ---------------------------------------------------------------------------
// Entry. Output layout: (out, q, k) flat: [0,16) out, then q, then k.
// ---------------------------------------------------------------------------
extern "C" void kernel_launch(void* const* d_in, const int* in_sizes, int n_in,
                              void* d_out, int out_size)
{
    const float* x     = (const float*)d_in[0];
    const float* W_qkv = (const float*)d_in[1];
    const float* b_qkv = (const float*)d_in[2];
    const float* W1    = (const float*)d_in[3];
    const float* b1    = (const float*)d_in[4];
    const float* W2    = (const float*)d_in[5];
    const float* b2    = (const float*)d_in[6];
    const float* W3    = (const float*)d_in[7];
    const float* b3    = (const float*)d_in[8];

    float* out   = (float*)d_out;
    float* q_out = out + 16;
    float* k_out = out + 16 + (size_t)NROWS * D_;

    cudaFuncSetAttribute(qkv_mma, cudaFuncAttributeMaxDynamicSharedMemorySize, QKV_SMEM);

    convert_x<<<(NROWS * D_ / 4) / 256, 256>>>(x);
    convert_w<<<(D_ * NC) / 256, 256>>>(W_qkv);
    qkv_mma<<<dim3(NC / TN, NROWS / TM), 256, QKV_SMEM>>>(b_qkv, q_out, k_out);
    scores_kernel<<<NROWS / 8, 256>>>(q_out, k_out);
    softmax_kernel<<<B_, 512>>>();
    sa_part_kernel<<<dim3(B_, 32), 512>>>();
    sa_reduce_kernel<<<B_, D_>>>(x);
    mlp1_kernel<<<dim3(B_, M_ / 256), 256>>>(W1, b1);
    mlp2_kernel<<<dim3(B_, M_ / 256), 256>>>(W2, b2);
    mlp3_kernel<<<1, 512>>>(W3, b3, out);
}

// round 9
// speedup vs baseline: 1.6061x; 1.4601x over previous
#include <cuda_runtime.h>
#include <cuda_fp16.h>
#include <cstdint>

// Problem dims
constexpr int B_ = 16, S_ = 4096, D_ = 512, M_ = 2048;
constexpr int NROWS = B_ * S_;   // 65536
constexpr int NQK   = 2 * D_;    // 1024 (q and k only; v is never materialized)

// ---------------------------------------------------------------------------
// Scratch (device globals: no allocations allowed)
// ---------------------------------------------------------------------------
__device__ __half g_xh[(size_t)NROWS * D_];        // x in fp16
__device__ __half g_wh[(size_t)NQK * D_];          // W_qk^T fp16 [n][k]
__device__ float g_u[B_ * D_];                     // W_k @ q_last  (per batch)
__device__ float g_c[B_];                          // q_last . b_k
__device__ float g_scores[NROWS];
__device__ float g_attn[NROWS];
__device__ float g_part[B_ * 32 * D_];
__device__ float g_y[B_ * D_];                     // sum_s attn * x
__device__ float g_h[B_ * D_];
__device__ float g_h1[B_ * M_];
__device__ float g_h2[B_ * M_];

// ---------------------------------------------------------------------------
// Helpers (baseline PTX: ldmatrix / mma.sync / cp.async — sm_80+)
// ---------------------------------------------------------------------------
__device__ __forceinline__ uint32_t smem_u32(const void* p) {
    uint32_t a;
    asm("{ .reg .u64 t; cvta.to.shared.u64 t, %1; cvt.u32.u64 %0, t; }"
        : "=r"(a) : "l"(p));
    return a;
}

// Swizzle<2,4,3> for 64-byte rows: bits[5:4] ^= bits[8:7]
#define SWZ64(o) ((o) ^ ((((uint32_t)(o)) >> 3) & 0x30u))

__device__ __forceinline__ void cp_async16(uint32_t sdst, const void* gsrc) {
    asm volatile("cp.async.cg.shared.global [%0], [%1], 16;"
                 :: "r"(sdst), "l"(gsrc) : "memory");
}
#define CP_COMMIT() asm volatile("cp.async.commit_group;" ::: "memory")
#define CP_WAIT(n)  asm volatile("cp.async.wait_group %0;" :: "n"(n) : "memory")

__device__ __forceinline__ void ldm_x4(uint32_t* r, uint32_t addr) {
    asm volatile("ldmatrix.sync.aligned.m8n8.x4.shared.b16 {%0,%1,%2,%3}, [%4];"
                 : "=r"(r[0]), "=r"(r[1]), "=r"(r[2]), "=r"(r[3]) : "r"(addr));
}

// fp16 inputs, fp32 accumulators
__device__ __forceinline__ void mma_f32acc(float* c, const uint32_t* a, const uint32_t* b) {
    asm volatile(
        "mma.sync.aligned.m16n8k16.row.col.f32.f16.f16.f32 "
        "{%0,%1,%2,%3}, {%4,%5,%6,%7}, {%8,%9}, {%0,%1,%2,%3};"
        : "+f"(c[0]), "+f"(c[1]), "+f"(c[2]), "+f"(c[3])
        : "r"(a[0]), "r"(a[1]), "r"(a[2]), "r"(a[3]), "r"(b[0]), "r"(b[1]));
}

// ---------------------------------------------------------------------------
// fp32 -> fp16 conversions
// ---------------------------------------------------------------------------
__global__ void convert_x(const float* __restrict__ x)
{
    const size_t i = (size_t)blockIdx.x * blockDim.x + threadIdx.x;  // float4 idx
    const float4 v = ((const float4*)x)[i];
    ((__half2*)g_xh)[i * 2 + 0] = __halves2half2(__float2half_rn(v.x), __float2half_rn(v.y));
    ((__half2*)g_xh)[i * 2 + 1] = __halves2half2(__float2half_rn(v.z), __float2half_rn(v.w));
}

// W_qkv is [512 x 1536] row-major; take first 1024 cols (q,k), store
// transposed [n][k] as fp16.
__global__ void convert_w(const float* __restrict__ W)
{
    const int e = blockIdx.x * blockDim.x + threadIdx.x;   // < 512*1024
    const int k = e >> 10, n = e & 1023;
    g_wh[(size_t)n * D_ + k] = __float2half_rn(W[(size_t)k * 1536 + n]);
}

// ---------------------------------------------------------------------------
// QK GEMM via single-pass fp16 mma.sync (fp32 accumulators):
//   C[65536 x 1024] = x[65536 x 512] @ W_qk[512 x 1024] + b
// CTA tile 128x64, warp tile 32x32 (8 warps, 4x2), K-chunk 32,
// 3-stage cp.async pipeline, 36KB dynamic smem, 2 CTAs/SM.
// ---------------------------------------------------------------------------
constexpr int TM = 128, TN = 64, TK = 32;
constexpr int NCHUNK = D_ / TK;  // 16
constexpr int A_TILE = 128 * 64;                       // 8 KB
constexpr int B_TILE = 64 * 64;                        // 4 KB
constexpr int OFF_AH = 0;
constexpr int OFF_BH = OFF_AH + A_TILE;
constexpr int STAGE_BYTES = OFF_BH + B_TILE;           // 12 KB
constexpr int QKV_SMEM    = 3 * STAGE_BYTES;           // 36 KB dynamic

__global__ __launch_bounds__(256, 2)
void qk_mma(const float* __restrict__ bias,
            float* __restrict__ q_out, float* __restrict__ k_out)
{
    extern __shared__ __align__(128) uint8_t sm[];
    const uint32_t sb = smem_u32(sm);

    const int tid  = threadIdx.x;
    const int warp = tid >> 5, lane = tid & 31;
    const int n0 = blockIdx.x * TN;
    const int m0 = blockIdx.y * TM;
    const int wm = (warp >> 1) * 32;       // warp row offset (0..96)
    const int wn = (warp & 1) * 32;        // warp col offset (0 or 32)

    // cp.async coords
    const int rl = tid >> 2;               // rows 0..63
    const int cl = tid & 3;                // 16B col 0..3
    const uint32_t soA0 = SWZ64(rl * 64 + cl * 16);
    const uint32_t soA1 = SWZ64((rl + 64) * 64 + cl * 16);

    auto load_stage = [&](int stage, int ch) {
        const uint32_t s0 = sb + stage * STAGE_BYTES;
        const int kcol = ch * TK + cl * 8;
        const size_t ga0 = (size_t)(m0 + rl) * D_ + kcol;
        const size_t ga1 = (size_t)(m0 + rl + 64) * D_ + kcol;
        const size_t gb  = (size_t)(n0 + rl) * D_ + kcol;
        cp_async16(s0 + OFF_AH + soA0, g_xh + ga0);
        cp_async16(s0 + OFF_AH + soA1, g_xh + ga1);
        cp_async16(s0 + OFF_BH + soA0, g_wh + gb);
    };

    float acc[2][4][4];
    #pragma unroll
    for (int i = 0; i < 2; i++)
        #pragma unroll
        for (int j = 0; j < 4; j++)
            #pragma unroll
            for (int e = 0; e < 4; e++) acc[i][j][e] = 0.f;

    // ldmatrix lane addressing components
    const uint32_t a_row = (lane & 15);                       // + wm + mf*16
    const uint32_t a_byt = (lane >> 4) << 4;                  // + kk*32
    const uint32_t b_row = ((lane >> 4) << 3) + (lane & 7);   // + wn + p*16
    const uint32_t b_byt = ((lane >> 3) & 1) << 4;            // + kk*32

    load_stage(0, 0); CP_COMMIT();
    load_stage(1, 1); CP_COMMIT();

    for (int ch = 0; ch < NCHUNK; ch++) {
        if (ch + 2 < NCHUNK) {
            load_stage((ch + 2) % 3, ch + 2); CP_COMMIT();
            CP_WAIT(2);
        } else {
            CP_WAIT(0);
        }
        __syncthreads();

        const uint32_t s0 = sb + (ch % 3) * STAGE_BYTES;

        #pragma unroll
        for (int kk = 0; kk < 2; kk++) {
            uint32_t ah[2][4];
            #pragma unroll
            for (int mf = 0; mf < 2; mf++) {
                const uint32_t ra = SWZ64((uint32_t)(wm + mf * 16 + a_row) * 64
                                          + kk * 32 + a_byt);
                ldm_x4(ah[mf], s0 + OFF_AH + ra);
            }
            uint32_t bh[4][2];
            #pragma unroll
            for (int p = 0; p < 2; p++) {
                const uint32_t rb = SWZ64((uint32_t)(wn + p * 16 + b_row) * 64
                                          + kk * 32 + b_byt);
                uint32_t t[4];
                ldm_x4(t, s0 + OFF_BH + rb);
                bh[p * 2][0] = t[0]; bh[p * 2][1] = t[1];
                bh[p * 2 + 1][0] = t[2]; bh[p * 2 + 1][1] = t[3];
            }
            #pragma unroll
            for (int mf = 0; mf < 2; mf++)
                #pragma unroll
                for (int nf = 0; nf < 4; nf++) mma_f32acc(acc[mf][nf], ah[mf], bh[nf]);
        }
        __syncthreads();
    }

    // Epilogue: acc + bias -> float2 global stores, route q/k per CTA
    const int region = n0 >> 9;                 // 0=q, 1=k
    float* dst = region ? k_out : q_out;
    const int cbase = n0 - region * 512;

    #pragma unroll
    for (int mf = 0; mf < 2; mf++) {
        #pragma unroll
        for (int nf = 0; nf < 4; nf++) {
            const int colg = n0 + wn + nf * 8 + (lane & 3) * 2;
            const float2 bv = *(const float2*)(bias + colg);
            const int col = cbase + wn + nf * 8 + (lane & 3) * 2;
            const int r0 = m0 + wm + mf * 16 + (lane >> 2);
            float2 v0 = make_float2(acc[mf][nf][0] + bv.x, acc[mf][nf][1] + bv.y);
            float2 v1 = make_float2(acc[mf][nf][2] + bv.x, acc[mf][nf][3] + bv.y);
            *(float2*)(dst + (size_t)r0 * D_ + col)       = v0;
            *(float2*)(dst + (size_t)(r0 + 8) * D_ + col) = v1;
        }
    }
}

// ---------------------------------------------------------------------------
// fp32 exact path for output 0:
// q_last[b] = x[b,S-1] @ W_q + b_q
// u[b][j]   = sum_d W_k[j][d] * q_last[d]   (row j of W_k = W[j*1536+512..])
// c[b]      = q_last[b] . b_k
// ---------------------------------------------------------------------------
__global__ __launch_bounds__(512)
void qlast_u_kernel(const float* __restrict__ x, const float* __restrict__ W,
                    const float* __restrict__ bq)
{
    __shared__ float xs[D_];
    __shared__ float ql[D_];
    __shared__ float red[D_];
    const int b = blockIdx.x, d = threadIdx.x;

    xs[d] = x[((size_t)b * S_ + (S_ - 1)) * D_ + d];
    __syncthreads();

    float acc = bq[d];
    #pragma unroll 8
    for (int k = 0; k < D_; k++) acc = fmaf(xs[k], W[(size_t)k * 1536 + d], acc);
    ql[d] = acc;
    __syncthreads();

    // u[d] = row d of W_k dotted with q_last: sum_k W[d*1536 + 512 + k] * ql[k]
    const float* wrow = W + (size_t)d * 1536 + 512;
    float acc2 = 0.f;
    #pragma unroll 8
    for (int k = 0; k < D_; k++) acc2 = fmaf(ql[k], wrow[k], acc2);
    g_u[b * D_ + d] = acc2;

    red[d] = ql[d] * bq[512 + d];
    __syncthreads();
    for (int s = 256; s; s >>= 1) {
        if (d < s) red[d] += red[d + s];
        __syncthreads();
    }
    if (d == 0) g_c[b] = red[0];
}

// ---------------------------------------------------------------------------
// scores[b,s] = u[b] . x[b,s] + c[b]     (one warp per (b,s); all fp32)
// ---------------------------------------------------------------------------
__global__ void scores_kernel(const float* __restrict__ x)
{
    const int gw   = (blockIdx.x * blockDim.x + threadIdx.x) >> 5;
    const int lane = threadIdx.x & 31;
    const int b    = gw >> 12;

    const float4* ur = (const float4*)(g_u + b * D_);
    const float4* xr = (const float4*)(x + (size_t)gw * D_);

    float acc = 0.f;
    #pragma unroll
    for (int it = 0; it < 4; it++) {
        float4 uv = ur[lane + it * 32];
        float4 xv = xr[lane + it * 32];
        acc += uv.x * xv.x + uv.y * xv.y + uv.z * xv.z + uv.w * xv.w;
    }
    #pragma unroll
    for (int off = 16; off; off >>= 1) acc += __shfl_xor_sync(0xffffffffu, acc, off);
    if (lane == 0) g_scores[gw] = acc + g_c[b];
}

__global__ void softmax_kernel()
{
    __shared__ float red[512];
    const int b = blockIdx.x, tid = threadIdx.x;
    const float* sc = g_scores + (size_t)b * S_;

    float lm = -1e30f;
    for (int i = tid; i < S_; i += 512) lm = fmaxf(lm, sc[i]);
    red[tid] = lm; __syncthreads();
    for (int s = 256; s; s >>= 1) {
        if (tid < s) red[tid] = fmaxf(red[tid], red[tid + s]);
        __syncthreads();
    }
    const float mx = red[0];
    __syncthreads();

    float ls = 0.f;
    for (int i = tid; i < S_; i += 512) {
        float e = expf(sc[i] - mx);
        g_attn[(size_t)b * S_ + i] = e;
        ls += e;
    }
    red[tid] = ls; __syncthreads();
    for (int s = 256; s; s >>= 1) {
        if (tid < s) red[tid] += red[tid + s];
        __syncthreads();
    }
    const float inv = 1.f / red[0];
    for (int i = tid; i < S_; i += 512) g_attn[(size_t)b * S_ + i] *= inv;
}

// ---------------------------------------------------------------------------
// y[b] = sum_s attn[b,s] * x[b,s]   (partials over 128-row chunks, then reduce)
// ---------------------------------------------------------------------------
__global__ void y_part_kernel(const float* __restrict__ x)
{
    const int b = blockIdx.x, ch = blockIdx.y, d = threadIdx.x;
    const float* xp = x + ((size_t)b * S_ + ch * 128) * D_ + d;
    const float* ap = g_attn + (size_t)b * S_ + ch * 128;
    float a0 = 0.f, a1 = 0.f;
    #pragma unroll 8
    for (int s = 0; s < 128; s += 2) {
        a0 = fmaf(ap[s],     xp[(size_t)s * D_],        a0);
        a1 = fmaf(ap[s + 1], xp[(size_t)(s + 1) * D_],  a1);
    }
    g_part[(b * 32 + ch) * D_ + d] = a0 + a1;
}

__global__ void y_reduce_kernel()
{
    const int b = blockIdx.x, d = threadIdx.x;
    float acc = 0.f;
    #pragma unroll
    for (int ch = 0; ch < 32; ch++) acc += g_part[(b * 32 + ch) * D_ + d];
    g_y[b * D_ + d] = acc;
}

// h[b] = x[b,S-1] + y[b] @ W_v + b_v      (fp32 exact; sum over W rows)
__global__ __launch_bounds__(512)
void h_kernel(const float* __restrict__ x, const float* __restrict__ W,
              const float* __restrict__ bq)
{
    __shared__ float ys[D_];
    const int b = blockIdx.x, d = threadIdx.x;
    ys[d] = g_y[b * D_ + d];
    __syncthreads();
    float acc = x[((size_t)b * S_ + (S_ - 1)) * D_ + d] + bq[1024 + d];
    #pragma unroll 8
    for (int k = 0; k < D_; k++) acc = fmaf(ys[k], W[(size_t)k * 1536 + 1024 + d], acc);
    g_h[b * D_ + d] = acc;
}

// ---------------------------------------------------------------------------
// MLP layers (fp32)
// ---------------------------------------------------------------------------
__global__ __launch_bounds__(256)
void mlp1_kernel(const float* __restrict__ W1, const float* __restrict__ b1)
{
    __shared__ float hs[D_];
    const int b = blockIdx.x, tid = threadIdx.x;
    hs[tid]       = g_h[b * D_ + tid];
    hs[tid + 256] = g_h[b * D_ + tid + 256];
    __syncthreads();
    const int m = blockIdx.y * 256 + tid;
    float acc = b1[m];
    #pragma unroll 8
    for (int k = 0; k < D_; k++) acc = fmaf(hs[k], W1[(size_t)k * M_ + m], acc);
    g_h1[b * M_ + m] = fmaxf(acc, 0.f);
}

__global__ __launch_bounds__(256)
void mlp2_kernel(const float* __restrict__ W2, const float* __restrict__ b2)
{
    __shared__ float hs[M_];
    const int b = blockIdx.x, tid = threadIdx.x;
    for (int i = tid; i < M_; i += 256) hs[i] = g_h1[b * M_ + i];
    __syncthreads();
    const int m = blockIdx.y * 256 + tid;
    float acc = b2[m];
    #pragma unroll 8
    for (int k = 0; k < M_; k++) acc = fmaf(hs[k], W2[(size_t)k * M_ + m], acc);
    g_h2[b * M_ + m] = fmaxf(acc, 0.f);
}

__global__ void mlp3_kernel(const float* __restrict__ W3, const float* __restrict__ b3,
                            float* __restrict__ out)
{
    const int w = threadIdx.x >> 5, lane = threadIdx.x & 31;
    float acc = 0.f;
    #pragma unroll
    for (int i = 0; i < M_ / 32; i++)
        acc = fmaf(g_h2[w * M_ + lane + i * 32], W3[lane + i * 32], acc);
    #pragma unroll
    for (int off = 16; off; off >>= 1) acc += __shfl_xor_sync(0xffffffffu, acc, off);
    if (lane == 0) out[w] = acc + b3[0];
}

// ---------------------------------------------------------------------------
// Entry. Output layout: (out, q, k) flat: [0,16) out, then q, then k.
// ---------------------------------------------------------------------------
extern "C" void kernel_launch(void* const* d_in, const int* in_sizes, int n_in,
                              void* d_out, int out_size)
{
    const float* x     = (const float*)d_in[0];
    const float* W_qkv = (const float*)d_in[1];
    const float* b_qkv = (const float*)d_in[2];
    const float* W1    = (const float*)d_in[3];
    const float* b1    = (const float*)d_in[4];
    const float* W2    = (const float*)d_in[5];
    const float* b2    = (const float*)d_in[6];
    const float* W3    = (const float*)d_in[7];
    const float* b3    = (const float*)d_in[8];

    float* out   = (float*)d_out;
    float* q_out = out + 16;
    float* k_out = out + 16 + (size_t)NROWS * D_;

    cudaFuncSetAttribute(qk_mma, cudaFuncAttributeMaxDynamicSharedMemorySize, QKV_SMEM);

    convert_x<<<(NROWS * D_ / 4) / 256, 256>>>(x);
    convert_w<<<(D_ * NQK) / 256, 256>>>(W_qkv);
    qk_mma<<<dim3(NQK / TN, NROWS / TM), 256, QKV_SMEM>>>(b_qkv, q_out, k_out);

    // fp32 exact path for output 0 (independent of the fp16 GEMM)
    qlast_u_kernel<<<B_, 512>>>(x, W_qkv, b_qkv);
    scores_kernel<<<NROWS / 8, 256>>>(x);
    softmax_kernel<<<B_, 512>>>();
    y_part_kernel<<<dim3(B_, 32), 512>>>(x);
    y_reduce_kernel<<<B_, D_>>>();
    h_kernel<<<B_, 512>>>(x, W_qkv, b_qkv);
    mlp1_kernel<<<dim3(B_, M_ / 256), 256>>>(W1, b1);
    mlp2_kernel<<<dim3(B_, M_ / 256), 256>>>(W2, b2);
    mlp3_kernel<<<1, 512>>>(W3, b3, out);
}

// round 10
// speedup vs baseline: 1.9431x; 1.2099x over previous
#include <cuda_runtime.h>
#include <cuda_fp16.h>
#include <cstdint>

// Problem dims
constexpr int B_ = 16, S_ = 4096, D_ = 512, M_ = 2048;
constexpr int NROWS = B_ * S_;   // 65536
constexpr int NQK   = 2 * D_;    // 1024 (q and k only; v is never materialized)

// ---------------------------------------------------------------------------
// Scratch (device globals: no allocations allowed)
// ---------------------------------------------------------------------------
__device__ __half g_xh[(size_t)NROWS * D_];        // x in fp16
__device__ __half g_wh[(size_t)NQK * D_];          // W_qk^T fp16 [n][k]
__device__ float g_ql[B_ * D_];                    // q_last (fp32 exact)
__device__ float g_u[B_ * D_];                     // W_k @ q_last  (per batch)
__device__ float g_c[B_];                          // q_last . b_k
__device__ float g_scores[NROWS];
__device__ float g_attn[NROWS];
__device__ float g_part[B_ * 32 * D_];
__device__ float g_y[B_ * D_];                     // sum_s attn * x
__device__ float g_h[B_ * D_];
__device__ float g_h1[B_ * M_];
__device__ float g_h2[B_ * M_];

// ---------------------------------------------------------------------------
// Helpers (baseline PTX: ldmatrix / mma.sync / cp.async — sm_80+)
// ---------------------------------------------------------------------------
__device__ __forceinline__ uint32_t smem_u32(const void* p) {
    uint32_t a;
    asm("{ .reg .u64 t; cvta.to.shared.u64 t, %1; cvt.u32.u64 %0, t; }"
        : "=r"(a) : "l"(p));
    return a;
}

// Swizzle<2,4,3> for 64-byte rows: bits[5:4] ^= bits[8:7]
#define SWZ64(o) ((o) ^ ((((uint32_t)(o)) >> 3) & 0x30u))

__device__ __forceinline__ void cp_async16(uint32_t sdst, const void* gsrc) {
    asm volatile("cp.async.cg.shared.global [%0], [%1], 16;"
                 :: "r"(sdst), "l"(gsrc) : "memory");
}
#define CP_COMMIT() asm volatile("cp.async.commit_group;" ::: "memory")
#define CP_WAIT(n)  asm volatile("cp.async.wait_group %0;" :: "n"(n) : "memory")

__device__ __forceinline__ void ldm_x4(uint32_t* r, uint32_t addr) {
    asm volatile("ldmatrix.sync.aligned.m8n8.x4.shared.b16 {%0,%1,%2,%3}, [%4];"
                 : "=r"(r[0]), "=r"(r[1]), "=r"(r[2]), "=r"(r[3]) : "r"(addr));
}

// fp16 inputs, fp32 accumulators
__device__ __forceinline__ void mma_f32acc(float* c, const uint32_t* a, const uint32_t* b) {
    asm volatile(
        "mma.sync.aligned.m16n8k16.row.col.f32.f16.f16.f32 "
        "{%0,%1,%2,%3}, {%4,%5,%6,%7}, {%8,%9}, {%0,%1,%2,%3};"
        : "+f"(c[0]), "+f"(c[1]), "+f"(c[2]), "+f"(c[3])
        : "r"(a[0]), "r"(a[1]), "r"(a[2]), "r"(a[3]), "r"(b[0]), "r"(b[1]));
}

// ---------------------------------------------------------------------------
// fp32 -> fp16 conversions
// ---------------------------------------------------------------------------
__global__ void convert_x(const float* __restrict__ x)
{
    const size_t i = (size_t)blockIdx.x * blockDim.x + threadIdx.x;  // float4 idx
    const float4 v = ((const float4*)x)[i];
    ((__half2*)g_xh)[i * 2 + 0] = __halves2half2(__float2half_rn(v.x), __float2half_rn(v.y));
    ((__half2*)g_xh)[i * 2 + 1] = __halves2half2(__float2half_rn(v.z), __float2half_rn(v.w));
}

// W_qkv is [512 x 1536] row-major; take first 1024 cols (q,k), store
// transposed [n][k] as fp16.
__global__ void convert_w(const float* __restrict__ W)
{
    const int e = blockIdx.x * blockDim.x + threadIdx.x;   // < 512*1024
    const int k = e >> 10, n = e & 1023;
    g_wh[(size_t)n * D_ + k] = __float2half_rn(W[(size_t)k * 1536 + n]);
}

// ---------------------------------------------------------------------------
// QK GEMM via single-pass fp16 mma.sync (fp32 accumulators):
//   C[65536 x 1024] = x[65536 x 512] @ W_qk[512 x 1024] + b
// CTA tile 128x64, warp tile 32x32 (8 warps, 4x2), K-chunk 32,
// 3-stage cp.async pipeline, 36KB dynamic smem, 2 CTAs/SM.
// ---------------------------------------------------------------------------
constexpr int TM = 128, TN = 64, TK = 32;
constexpr int NCHUNK = D_ / TK;  // 16
constexpr int A_TILE = 128 * 64;                       // 8 KB
constexpr int B_TILE = 64 * 64;                        // 4 KB
constexpr int OFF_AH = 0;
constexpr int OFF_BH = OFF_AH + A_TILE;
constexpr int STAGE_BYTES = OFF_BH + B_TILE;           // 12 KB
constexpr int QKV_SMEM    = 3 * STAGE_BYTES;           // 36 KB dynamic

__global__ __launch_bounds__(256, 2)
void qk_mma(const float* __restrict__ bias,
            float* __restrict__ q_out, float* __restrict__ k_out)
{
    extern __shared__ __align__(128) uint8_t sm[];
    const uint32_t sb = smem_u32(sm);

    const int tid  = threadIdx.x;
    const int warp = tid >> 5, lane = tid & 31;
    const int n0 = blockIdx.x * TN;
    const int m0 = blockIdx.y * TM;
    const int wm = (warp >> 1) * 32;       // warp row offset (0..96)
    const int wn = (warp & 1) * 32;        // warp col offset (0 or 32)

    // cp.async coords
    const int rl = tid >> 2;               // rows 0..63
    const int cl = tid & 3;                // 16B col 0..3
    const uint32_t soA0 = SWZ64(rl * 64 + cl * 16);
    const uint32_t soA1 = SWZ64((rl + 64) * 64 + cl * 16);

    auto load_stage = [&](int stage, int ch) {
        const uint32_t s0 = sb + stage * STAGE_BYTES;
        const int kcol = ch * TK + cl * 8;
        const size_t ga0 = (size_t)(m0 + rl) * D_ + kcol;
        const size_t ga1 = (size_t)(m0 + rl + 64) * D_ + kcol;
        const size_t gb  = (size_t)(n0 + rl) * D_ + kcol;
        cp_async16(s0 + OFF_AH + soA0, g_xh + ga0);
        cp_async16(s0 + OFF_AH + soA1, g_xh + ga1);
        cp_async16(s0 + OFF_BH + soA0, g_wh + gb);
    };

    float acc[2][4][4];
    #pragma unroll
    for (int i = 0; i < 2; i++)
        #pragma unroll
        for (int j = 0; j < 4; j++)
            #pragma unroll
            for (int e = 0; e < 4; e++) acc[i][j][e] = 0.f;

    // ldmatrix lane addressing components
    const uint32_t a_row = (lane & 15);                       // + wm + mf*16
    const uint32_t a_byt = (lane >> 4) << 4;                  // + kk*32
    const uint32_t b_row = ((lane >> 4) << 3) + (lane & 7);   // + wn + p*16
    const uint32_t b_byt = ((lane >> 3) & 1) << 4;            // + kk*32

    load_stage(0, 0); CP_COMMIT();
    load_stage(1, 1); CP_COMMIT();

    for (int ch = 0; ch < NCHUNK; ch++) {
        if (ch + 2 < NCHUNK) {
            load_stage((ch + 2) % 3, ch + 2); CP_COMMIT();
            CP_WAIT(2);
        } else {
            CP_WAIT(0);
        }
        __syncthreads();

        const uint32_t s0 = sb + (ch % 3) * STAGE_BYTES;

        #pragma unroll
        for (int kk = 0; kk < 2; kk++) {
            uint32_t ah[2][4];
            #pragma unroll
            for (int mf = 0; mf < 2; mf++) {
                const uint32_t ra = SWZ64((uint32_t)(wm + mf * 16 + a_row) * 64
                                          + kk * 32 + a_byt);
                ldm_x4(ah[mf], s0 + OFF_AH + ra);
            }
            uint32_t bh[4][2];
            #pragma unroll
            for (int p = 0; p < 2; p++) {
                const uint32_t rb = SWZ64((uint32_t)(wn + p * 16 + b_row) * 64
                                          + kk * 32 + b_byt);
                uint32_t t[4];
                ldm_x4(t, s0 + OFF_BH + rb);
                bh[p * 2][0] = t[0]; bh[p * 2][1] = t[1];
                bh[p * 2 + 1][0] = t[2]; bh[p * 2 + 1][1] = t[3];
            }
            #pragma unroll
            for (int mf = 0; mf < 2; mf++)
                #pragma unroll
                for (int nf = 0; nf < 4; nf++) mma_f32acc(acc[mf][nf], ah[mf], bh[nf]);
        }
        __syncthreads();
    }

    // Epilogue: acc + bias -> float2 global stores, route q/k per CTA
    const int region = n0 >> 9;                 // 0=q, 1=k
    float* dst = region ? k_out : q_out;
    const int cbase = n0 - region * 512;

    #pragma unroll
    for (int mf = 0; mf < 2; mf++) {
        #pragma unroll
        for (int nf = 0; nf < 4; nf++) {
            const int colg = n0 + wn + nf * 8 + (lane & 3) * 2;
            const float2 bv = *(const float2*)(bias + colg);
            const int col = cbase + wn + nf * 8 + (lane & 3) * 2;
            const int r0 = m0 + wm + mf * 16 + (lane >> 2);
            float2 v0 = make_float2(acc[mf][nf][0] + bv.x, acc[mf][nf][1] + bv.y);
            float2 v1 = make_float2(acc[mf][nf][2] + bv.x, acc[mf][nf][3] + bv.y);
            *(float2*)(dst + (size_t)r0 * D_ + col)       = v0;
            *(float2*)(dst + (size_t)(r0 + 8) * D_ + col) = v1;
        }
    }
}

// ---------------------------------------------------------------------------
// fp32 exact path for output 0:
// qlast_kernel: q_last[b] = x[b,S-1] @ W_q + b_q  (coalesced over d),
//               c[b] = q_last . b_k
// ---------------------------------------------------------------------------
__global__ __launch_bounds__(512)
void qlast_kernel(const float* __restrict__ x, const float* __restrict__ W,
                  const float* __restrict__ bq)
{
    __shared__ float xs[D_];
    __shared__ float red[D_];
    const int b = blockIdx.x, d = threadIdx.x;

    xs[d] = x[((size_t)b * S_ + (S_ - 1)) * D_ + d];
    __syncthreads();

    float acc = bq[d];
    #pragma unroll 8
    for (int k = 0; k < D_; k++) acc = fmaf(xs[k], W[(size_t)k * 1536 + d], acc);
    g_ql[b * D_ + d] = acc;

    red[d] = acc * bq[512 + d];
    __syncthreads();
    for (int s = 256; s; s >>= 1) {
        if (d < s) red[d] += red[d + s];
        __syncthreads();
    }
    if (d == 0) g_c[b] = red[0];
}

// u[b][j] = sum_k W_k[j][k] * q_last[b][k] — warp per j, lanes over k (coalesced)
__global__ __launch_bounds__(256)
void u_kernel(const float* __restrict__ W)
{
    __shared__ float qs[D_];
    const int b = blockIdx.y, tid = threadIdx.x;
    const int warp = tid >> 5, lane = tid & 31;
    qs[tid]       = g_ql[b * D_ + tid];
    qs[tid + 256] = g_ql[b * D_ + tid + 256];
    __syncthreads();

    const int j = blockIdx.x * 8 + warp;
    const float* wrow = W + (size_t)j * 1536 + 512;
    float acc = 0.f;
    #pragma unroll
    for (int i = 0; i < 16; i++)
        acc = fmaf(wrow[lane + i * 32], qs[lane + i * 32], acc);
    #pragma unroll
    for (int off = 16; off; off >>= 1) acc += __shfl_xor_sync(0xffffffffu, acc, off);
    if (lane == 0) g_u[b * D_ + j] = acc;
}

// ---------------------------------------------------------------------------
// scores[b,s] = u[b] . x[b,s] + c[b]     (one warp per (b,s); all fp32)
// ---------------------------------------------------------------------------
__global__ void scores_kernel(const float* __restrict__ x)
{
    const int gw   = (blockIdx.x * blockDim.x + threadIdx.x) >> 5;
    const int lane = threadIdx.x & 31;
    const int b    = gw >> 12;

    const float4* ur = (const float4*)(g_u + b * D_);
    const float4* xr = (const float4*)(x + (size_t)gw * D_);

    float acc = 0.f;
    #pragma unroll
    for (int it = 0; it < 4; it++) {
        float4 uv = ur[lane + it * 32];
        float4 xv = xr[lane + it * 32];
        acc += uv.x * xv.x + uv.y * xv.y + uv.z * xv.z + uv.w * xv.w;
    }
    #pragma unroll
    for (int off = 16; off; off >>= 1) acc += __shfl_xor_sync(0xffffffffu, acc, off);
    if (lane == 0) g_scores[gw] = acc + g_c[b];
}

__global__ void softmax_kernel()
{
    __shared__ float red[512];
    const int b = blockIdx.x, tid = threadIdx.x;
    const float* sc = g_scores + (size_t)b * S_;

    float lm = -1e30f;
    for (int i = tid; i < S_; i += 512) lm = fmaxf(lm, sc[i]);
    red[tid] = lm; __syncthreads();
    for (int s = 256; s; s >>= 1) {
        if (tid < s) red[tid] = fmaxf(red[tid], red[tid + s]);
        __syncthreads();
    }
    const float mx = red[0];
    __syncthreads();

    float ls = 0.f;
    for (int i = tid; i < S_; i += 512) {
        float e = expf(sc[i] - mx);
        g_attn[(size_t)b * S_ + i] = e;
        ls += e;
    }
    red[tid] = ls; __syncthreads();
    for (int s = 256; s; s >>= 1) {
        if (tid < s) red[tid] += red[tid + s];
        __syncthreads();
    }
    const float inv = 1.f / red[0];
    for (int i = tid; i < S_; i += 512) g_attn[(size_t)b * S_ + i] *= inv;
}

// ---------------------------------------------------------------------------
// y[b] = sum_s attn[b,s] * x[b,s]   (partials over 128-row chunks, then reduce)
// ---------------------------------------------------------------------------
__global__ void y_part_kernel(const float* __restrict__ x)
{
    const int b = blockIdx.x, ch = blockIdx.y, d = threadIdx.x;
    const float* xp = x + ((size_t)b * S_ + ch * 128) * D_ + d;
    const float* ap = g_attn + (size_t)b * S_ + ch * 128;
    float a0 = 0.f, a1 = 0.f;
    #pragma unroll 8
    for (int s = 0; s < 128; s += 2) {
        a0 = fmaf(ap[s],     xp[(size_t)s * D_],        a0);
        a1 = fmaf(ap[s + 1], xp[(size_t)(s + 1) * D_],  a1);
    }
    g_part[(b * 32 + ch) * D_ + d] = a0 + a1;
}

__global__ void y_reduce_kernel()
{
    const int b = blockIdx.x, d = threadIdx.x;
    float acc = 0.f;
    #pragma unroll
    for (int ch = 0; ch < 32; ch++) acc += g_part[(b * 32 + ch) * D_ + d];
    g_y[b * D_ + d] = acc;
}

// h[b] = x[b,S-1] + y[b] @ W_v + b_v      (fp32 exact; sum over W rows)
__global__ __launch_bounds__(512)
void h_kernel(const float* __restrict__ x, const float* __restrict__ W,
              const float* __restrict__ bq)
{
    __shared__ float ys[D_];
    const int b = blockIdx.x, d = threadIdx.x;
    ys[d] = g_y[b * D_ + d];
    __syncthreads();
    float acc = x[((size_t)b * S_ + (S_ - 1)) * D_ + d] + bq[1024 + d];
    #pragma unroll 8
    for (int k = 0; k < D_; k++) acc = fmaf(ys[k], W[(size_t)k * 1536 + 1024 + d], acc);
    g_h[b * D_ + d] = acc;
}

// ---------------------------------------------------------------------------
// MLP layers (fp32)
// ---------------------------------------------------------------------------
__global__ __launch_bounds__(256)
void mlp1_kernel(const float* __restrict__ W1, const float* __restrict__ b1)
{
    __shared__ float hs[D_];
    const int b = blockIdx.x, tid = threadIdx.x;
    hs[tid]       = g_h[b * D_ + tid];
    hs[tid + 256] = g_h[b * D_ + tid + 256];
    __syncthreads();
    const int m = blockIdx.y * 256 + tid;
    float acc = b1[m];
    #pragma unroll 8
    for (int k = 0; k < D_; k++) acc = fmaf(hs[k], W1[(size_t)k * M_ + m], acc);
    g_h1[b * M_ + m] = fmaxf(acc, 0.f);
}

__global__ __launch_bounds__(256)
void mlp2_kernel(const float* __restrict__ W2, const float* __restrict__ b2)
{
    __shared__ float hs[M_];
    const int b = blockIdx.x, tid = threadIdx.x;
    for (int i = tid; i < M_; i += 256) hs[i] = g_h1[b * M_ + i];
    __syncthreads();
    const int m = blockIdx.y * 256 + tid;
    float acc = b2[m];
    #pragma unroll 8
    for (int k = 0; k < M_; k++) acc = fmaf(hs[k], W2[(size_t)k * M_ + m], acc);
    g_h2[b * M_ + m] = fmaxf(acc, 0.f);
}

__global__ void mlp3_kernel(const float* __restrict__ W3, const float* __restrict__ b3,
                            float* __restrict__ out)
{
    const int w = threadIdx.x >> 5, lane = threadIdx.x & 31;
    float acc = 0.f;
    #pragma unroll
    for (int i = 0; i < M_ / 32; i++)
        acc = fmaf(g_h2[w * M_ + lane + i * 32], W3[lane + i * 32], acc);
    #pragma unroll
    for (int off = 16; off; off >>= 1) acc += __shfl_xor_sync(0xffffffffu, acc, off);
    if (lane == 0) out[w] = acc + b3[0];
}

// ---------------------------------------------------------------------------
// Entry. Output layout: (out, q, k) flat: [0,16) out, then q, then k.
// Launch order puts qk_mma 6th so ncu (-s 5 -c 1) profiles the GEMM.
// ---------------------------------------------------------------------------
extern "C" void kernel_launch(void* const* d_in, const int* in_sizes, int n_in,
                              void* d_out, int out_size)
{
    const float* x     = (const float*)d_in[0];
    const float* W_qkv = (const float*)d_in[1];
    const float* b_qkv = (const float*)d_in[2];
    const float* W1    = (const float*)d_in[3];
    const float* b1    = (const float*)d_in[4];
    const float* W2    = (const float*)d_in[5];
    const float* b2    = (const float*)d_in[6];
    const float* W3    = (const float*)d_in[7];
    const float* b3    = (const float*)d_in[8];

    float* out   = (float*)d_out;
    float* q_out = out + 16;
    float* k_out = out + 16 + (size_t)NROWS * D_;

    cudaFuncSetAttribute(qk_mma, cudaFuncAttributeMaxDynamicSharedMemorySize, QKV_SMEM);

    qlast_kernel<<<B_, 512>>>(x, W_qkv, b_qkv);                     // 1
    convert_x<<<(NROWS * D_ / 4) / 256, 256>>>(x);                  // 2
    convert_w<<<(D_ * NQK) / 256, 256>>>(W_qkv);                    // 3
    u_kernel<<<dim3(D_ / 8, B_), 256>>>(W_qkv);                     // 4
    scores_kernel<<<NROWS / 8, 256>>>(x);                           // 5
    qk_mma<<<dim3(NQK / TN, NROWS / TM), 256, QKV_SMEM>>>(b_qkv, q_out, k_out); // 6 (ncu)
    softmax_kernel<<<B_, 512>>>();
    y_part_kernel<<<dim3(B_, 32), 512>>>(x);
    y_reduce_kernel<<<B_, D_>>>();
    h_kernel<<<B_, 512>>>(x, W_qkv, b_qkv);
    mlp1_kernel<<<dim3(B_, M_ / 256), 256>>>(W1, b1);
    mlp2_kernel<<<dim3(B_, M_ / 256), 256>>>(W2, b2);
    mlp3_kernel<<<1, 512>>>(W3, b3, out);
}

// round 11
// speedup vs baseline: 2.1545x; 1.1088x over previous
#include <cuda_runtime.h>
#include <cuda_fp16.h>
#include <cstdint>

// Problem dims
constexpr int B_ = 16, S_ = 4096, D_ = 512, M_ = 2048;
constexpr int NROWS = B_ * S_;   // 65536
constexpr int NQK   = 2 * D_;    // 1024 (q and k only; v never materialized)

// ---------------------------------------------------------------------------
// Scratch (device globals: no allocations allowed)
// ---------------------------------------------------------------------------
__device__ __half g_xh[(size_t)NROWS * D_];        // x in fp16
__device__ __half g_wh[(size_t)NQK * D_];          // W_qk^T fp16 [n][k]
__device__ float g_ql[B_ * D_];                    // q_last (fp32 exact)
__device__ float g_u[B_ * D_];                     // W_k @ q_last
__device__ float g_c[B_];                          // q_last . b_k
__device__ float g_scores[NROWS];
__device__ float g_attn[NROWS];
__device__ float g_part[B_ * 32 * D_];
__device__ float g_y[B_ * D_];
__device__ float g_h[B_ * D_];
__device__ float g_h1[B_ * M_];
__device__ float g_h2[B_ * M_];

// ---------------------------------------------------------------------------
// Helpers (baseline PTX: ldmatrix / mma.sync / cp.async — sm_80+)
// ---------------------------------------------------------------------------
__device__ __forceinline__ uint32_t smem_u32(const void* p) {
    uint32_t a;
    asm("{ .reg .u64 t; cvta.to.shared.u64 t, %1; cvt.u32.u64 %0, t; }"
        : "=r"(a) : "l"(p));
    return a;
}

// Swizzle<3,4,3> for 128-byte rows: bits[6:4] ^= bits[9:7]
#define SWZ128(o) ((o) ^ ((((uint32_t)(o)) >> 3) & 0x70u))

__device__ __forceinline__ void cp_async16(uint32_t sdst, const void* gsrc) {
    asm volatile("cp.async.cg.shared.global [%0], [%1], 16;"
                 :: "r"(sdst), "l"(gsrc) : "memory");
}
#define CP_COMMIT() asm volatile("cp.async.commit_group;" ::: "memory")
#define CP_WAIT(n)  asm volatile("cp.async.wait_group %0;" :: "n"(n) : "memory")

__device__ __forceinline__ void ldm_x4(uint32_t* r, uint32_t addr) {
    asm volatile("ldmatrix.sync.aligned.m8n8.x4.shared.b16 {%0,%1,%2,%3}, [%4];"
                 : "=r"(r[0]), "=r"(r[1]), "=r"(r[2]), "=r"(r[3]) : "r"(addr));
}

__device__ __forceinline__ void mma_f32acc(float* c, const uint32_t* a, const uint32_t* b) {
    asm volatile(
        "mma.sync.aligned.m16n8k16.row.col.f32.f16.f16.f32 "
        "{%0,%1,%2,%3}, {%4,%5,%6,%7}, {%8,%9}, {%0,%1,%2,%3};"
        : "+f"(c[0]), "+f"(c[1]), "+f"(c[2]), "+f"(c[3])
        : "r"(a[0]), "r"(a[1]), "r"(a[2]), "r"(a[3]), "r"(b[0]), "r"(b[1]));
}

// ---------------------------------------------------------------------------
// fp32 exact path pieces (output 0)
// ---------------------------------------------------------------------------
__global__ __launch_bounds__(512)
void qlast_kernel(const float* __restrict__ x, const float* __restrict__ W,
                  const float* __restrict__ bq)
{
    __shared__ float xs[D_];
    __shared__ float red[D_];
    const int b = blockIdx.x, d = threadIdx.x;

    xs[d] = x[((size_t)b * S_ + (S_ - 1)) * D_ + d];
    __syncthreads();

    float acc = bq[d];
    #pragma unroll 8
    for (int k = 0; k < D_; k++) acc = fmaf(xs[k], W[(size_t)k * 1536 + d], acc);
    g_ql[b * D_ + d] = acc;

    red[d] = acc * bq[512 + d];
    __syncthreads();
    for (int s = 256; s; s >>= 1) {
        if (d < s) red[d] += red[d + s];
        __syncthreads();
    }
    if (d == 0) g_c[b] = red[0];
}

// u[b][j] = sum_k W_k[j][k] * q_last[b][k] — warp per j, lanes over k
__global__ __launch_bounds__(256)
void u_kernel(const float* __restrict__ W)
{
    __shared__ float qs[D_];
    const int b = blockIdx.y, tid = threadIdx.x;
    const int warp = tid >> 5, lane = tid & 31;
    qs[tid]       = g_ql[b * D_ + tid];
    qs[tid + 256] = g_ql[b * D_ + tid + 256];
    __syncthreads();

    const int j = blockIdx.x * 8 + warp;
    const float* wrow = W + (size_t)j * 1536 + 512;
    float acc = 0.f;
    #pragma unroll
    for (int i = 0; i < 16; i++)
        acc = fmaf(wrow[lane + i * 32], qs[lane + i * 32], acc);
    #pragma unroll
    for (int off = 16; off; off >>= 1) acc += __shfl_xor_sync(0xffffffffu, acc, off);
    if (lane == 0) g_u[b * D_ + j] = acc;
}

// ---------------------------------------------------------------------------
// scores + convert fusion:
//   scores[b,s] = u[b] . x[b,s] + c[b]  (warp per row)
//   g_xh[row]   = fp16(x[row])          (same pass)
//   g_wh        = fp16(W_qk^T)          (first 2048 blocks, 1 elem/thread)
// ---------------------------------------------------------------------------
__global__ void scores_cvt_kernel(const float* __restrict__ x,
                                  const float* __restrict__ W)
{
    // W conversion side-job: gtid < 512*1024
    const int gtid = blockIdx.x * 256 + threadIdx.x;
    if (gtid < D_ * NQK) {
        const int k = gtid >> 10, n = gtid & 1023;
        g_wh[(size_t)n * D_ + k] = __float2half_rn(W[(size_t)k * 1536 + n]);
    }

    const int gw   = (blockIdx.x * blockDim.x + threadIdx.x) >> 5;
    const int lane = threadIdx.x & 31;
    const int b    = gw >> 12;

    const float4* ur = (const float4*)(g_u + b * D_);
    const float4* xr = (const float4*)(x + (size_t)gw * D_);
    __half2* xo = (__half2*)(g_xh + (size_t)gw * D_);

    float acc = 0.f;
    #pragma unroll
    for (int it = 0; it < 4; it++) {
        const int e4 = lane + it * 32;
        float4 uv = ur[e4];
        float4 xv = xr[e4];
        acc += uv.x * xv.x + uv.y * xv.y + uv.z * xv.z + uv.w * xv.w;
        __half2 h0 = __halves2half2(__float2half_rn(xv.x), __float2half_rn(xv.y));
        __half2 h1 = __halves2half2(__float2half_rn(xv.z), __float2half_rn(xv.w));
        xo[e4 * 2]     = h0;
        xo[e4 * 2 + 1] = h1;
    }
    #pragma unroll
    for (int off = 16; off; off >>= 1) acc += __shfl_xor_sync(0xffffffffu, acc, off);
    if (lane == 0) g_scores[gw] = acc + g_c[b];
}

// ---------------------------------------------------------------------------
// QK GEMM via single-pass fp16 mma.sync (fp32 accumulators):
//   C[65536 x 1024] = x[65536 x 512] @ W_qk[512 x 1024] + b
// CTA tile 128x64, warp tile 32x32 (8 warps, 4x2), K-chunk 64 (SW128 rows),
// 3-stage cp.async pipeline, 72KB dynamic smem, 2 CTAs/SM.
// ---------------------------------------------------------------------------
constexpr int TM = 128, TN = 64, TK = 64;
constexpr int NCHUNK = D_ / TK;  // 8
constexpr int A_TILE = 128 * 128;                      // 16 KB
constexpr int B_TILE = 64 * 128;                       // 8 KB
constexpr int OFF_AH = 0;
constexpr int OFF_BH = OFF_AH + A_TILE;
constexpr int STAGE_BYTES = OFF_BH + B_TILE;           // 24 KB
constexpr int QKV_SMEM    = 3 * STAGE_BYTES;           // 72 KB dynamic

__global__ __launch_bounds__(256, 2)
void qk_mma(const float* __restrict__ bias,
            float* __restrict__ q_out, float* __restrict__ k_out)
{
    extern __shared__ __align__(128) uint8_t sm[];
    const uint32_t sb = smem_u32(sm);

    const int tid  = threadIdx.x;
    const int warp = tid >> 5, lane = tid & 31;
    const int n0 = blockIdx.x * TN;
    const int m0 = blockIdx.y * TM;
    const int wm = (warp >> 1) * 32;       // warp row offset (0..96)
    const int wn = (warp & 1) * 32;        // warp col offset (0 or 32)

    // cp.async coords: rows of 128B = 8 chunks of 16B
    const int rl = tid >> 3;               // 0..31 row group base
    const int cl = tid & 7;                // 16B col 0..7

    auto load_stage = [&](int stage, int ch) {
        const uint32_t s0 = sb + stage * STAGE_BYTES;
        const int kcol = ch * TK + cl * 8;
        // A: 128 rows x 8 chunks = 1024 chunks, 4 per thread
        #pragma unroll
        for (int j = 0; j < 4; j++) {
            const int row = rl + j * 32;
            const uint32_t so = SWZ128((uint32_t)row * 128 + cl * 16);
            cp_async16(s0 + OFF_AH + so, g_xh + (size_t)(m0 + row) * D_ + kcol);
        }
        // B: 64 rows x 8 chunks = 512 chunks, 2 per thread
        #pragma unroll
        for (int j = 0; j < 2; j++) {
            const int row = rl + j * 32;
            const uint32_t so = SWZ128((uint32_t)row * 128 + cl * 16);
            cp_async16(s0 + OFF_BH + so, g_wh + (size_t)(n0 + row) * D_ + kcol);
        }
    };

    float acc[2][4][4];
    #pragma unroll
    for (int i = 0; i < 2; i++)
        #pragma unroll
        for (int j = 0; j < 4; j++)
            #pragma unroll
            for (int e = 0; e < 4; e++) acc[i][j][e] = 0.f;

    // ldmatrix lane addressing components
    const uint32_t a_row = (lane & 15);                       // + wm + mf*16
    const uint32_t a_byt = (lane >> 4) << 4;                  // + kk*32
    const uint32_t b_row = ((lane >> 4) << 3) + (lane & 7);   // + wn + p*16
    const uint32_t b_byt = ((lane >> 3) & 1) << 4;            // + kk*32

    load_stage(0, 0); CP_COMMIT();
    load_stage(1, 1); CP_COMMIT();

    for (int ch = 0; ch < NCHUNK; ch++) {
        if (ch + 2 < NCHUNK) {
            load_stage((ch + 2) % 3, ch + 2); CP_COMMIT();
            CP_WAIT(2);
        } else {
            CP_WAIT(0);
        }
        __syncthreads();

        const uint32_t s0 = sb + (ch % 3) * STAGE_BYTES;

        #pragma unroll
        for (int kk = 0; kk < 4; kk++) {
            uint32_t ah[2][4];
            #pragma unroll
            for (int mf = 0; mf < 2; mf++) {
                const uint32_t ra = SWZ128((uint32_t)(wm + mf * 16 + a_row) * 128
                                           + kk * 32 + a_byt);
                ldm_x4(ah[mf], s0 + OFF_AH + ra);
            }
            uint32_t bh[4][2];
            #pragma unroll
            for (int p = 0; p < 2; p++) {
                const uint32_t rb = SWZ128((uint32_t)(wn + p * 16 + b_row) * 128
                                           + kk * 32 + b_byt);
                uint32_t t[4];
                ldm_x4(t, s0 + OFF_BH + rb);
                bh[p * 2][0] = t[0]; bh[p * 2][1] = t[1];
                bh[p * 2 + 1][0] = t[2]; bh[p * 2 + 1][1] = t[3];
            }
            #pragma unroll
            for (int mf = 0; mf < 2; mf++)
                #pragma unroll
                for (int nf = 0; nf < 4; nf++) mma_f32acc(acc[mf][nf], ah[mf], bh[nf]);
        }
        __syncthreads();
    }

    // Epilogue: acc + bias -> float2 global stores, route q/k per CTA
    const int region = n0 >> 9;                 // 0=q, 1=k
    float* dst = region ? k_out : q_out;
    const int cbase = n0 - region * 512;

    #pragma unroll
    for (int mf = 0; mf < 2; mf++) {
        #pragma unroll
        for (int nf = 0; nf < 4; nf++) {
            const int colg = n0 + wn + nf * 8 + (lane & 3) * 2;
            const float2 bv = *(const float2*)(bias + colg);
            const int col = cbase + wn + nf * 8 + (lane & 3) * 2;
            const int r0 = m0 + wm + mf * 16 + (lane >> 2);
            float2 v0 = make_float2(acc[mf][nf][0] + bv.x, acc[mf][nf][1] + bv.y);
            float2 v1 = make_float2(acc[mf][nf][2] + bv.x, acc[mf][nf][3] + bv.y);
            *(float2*)(dst + (size_t)r0 * D_ + col)       = v0;
            *(float2*)(dst + (size_t)(r0 + 8) * D_ + col) = v1;
        }
    }
}

// ---------------------------------------------------------------------------
// softmax over S per batch
// ---------------------------------------------------------------------------
__global__ void softmax_kernel()
{
    __shared__ float red[512];
    const int b = blockIdx.x, tid = threadIdx.x;
    const float* sc = g_scores + (size_t)b * S_;

    float lm = -1e30f;
    for (int i = tid; i < S_; i += 512) lm = fmaxf(lm, sc[i]);
    red[tid] = lm; __syncthreads();
    for (int s = 256; s; s >>= 1) {
        if (tid < s) red[tid] = fmaxf(red[tid], red[tid + s]);
        __syncthreads();
    }
    const float mx = red[0];
    __syncthreads();

    float ls = 0.f;
    for (int i = tid; i < S_; i += 512) {
        float e = expf(sc[i] - mx);
        g_attn[(size_t)b * S_ + i] = e;
        ls += e;
    }
    red[tid] = ls; __syncthreads();
    for (int s = 256; s; s >>= 1) {
        if (tid < s) red[tid] += red[tid + s];
        __syncthreads();
    }
    const float inv = 1.f / red[0];
    for (int i = tid; i < S_; i += 512) g_attn[(size_t)b * S_ + i] *= inv;
}

// y[b] = sum_s attn[b,s] * x[b,s]
__global__ void y_part_kernel(const float* __restrict__ x)
{
    const int b = blockIdx.x, ch = blockIdx.y, d = threadIdx.x;
    const float* xp = x + ((size_t)b * S_ + ch * 128) * D_ + d;
    const float* ap = g_attn + (size_t)b * S_ + ch * 128;
    float a0 = 0.f, a1 = 0.f;
    #pragma unroll 8
    for (int s = 0; s < 128; s += 2) {
        a0 = fmaf(ap[s],     xp[(size_t)s * D_],        a0);
        a1 = fmaf(ap[s + 1], xp[(size_t)(s + 1) * D_],  a1);
    }
    g_part[(b * 32 + ch) * D_ + d] = a0 + a1;
}

__global__ void y_reduce_kernel()
{
    const int b = blockIdx.x, d = threadIdx.x;
    float acc = 0.f;
    #pragma unroll
    for (int ch = 0; ch < 32; ch++) acc += g_part[(b * 32 + ch) * D_ + d];
    g_y[b * D_ + d] = acc;
}

// h[b] = x[b,S-1] + y[b] @ W_v + b_v
__global__ __launch_bounds__(512)
void h_kernel(const float* __restrict__ x, const float* __restrict__ W,
              const float* __restrict__ bq)
{
    __shared__ float ys[D_];
    const int b = blockIdx.x, d = threadIdx.x;
    ys[d] = g_y[b * D_ + d];
    __syncthreads();
    float acc = x[((size_t)b * S_ + (S_ - 1)) * D_ + d] + bq[1024 + d];
    #pragma unroll 8
    for (int k = 0; k < D_; k++) acc = fmaf(ys[k], W[(size_t)k * 1536 + 1024 + d], acc);
    g_h[b * D_ + d] = acc;
}

// ---------------------------------------------------------------------------
// MLP layers (fp32), batch-tiled: 4 batches per weight read
// ---------------------------------------------------------------------------
__global__ __launch_bounds__(256)
void mlp1_kernel(const float* __restrict__ W1, const float* __restrict__ b1)
{
    __shared__ float hs[4][D_];
    const int bg = blockIdx.y * 4, tid = threadIdx.x;
    #pragma unroll
    for (int i = 0; i < 8; i++) {
        const int idx = tid + i * 256;          // < 2048
        hs[idx >> 9][idx & 511] = g_h[(bg + (idx >> 9)) * D_ + (idx & 511)];
    }
    __syncthreads();
    const int m = blockIdx.x * 256 + tid;
    float a0 = b1[m], a1 = a0, a2 = a0, a3 = a0;
    #pragma unroll 8
    for (int k = 0; k < D_; k++) {
        const float w = W1[(size_t)k * M_ + m];
        a0 = fmaf(hs[0][k], w, a0);
        a1 = fmaf(hs[1][k], w, a1);
        a2 = fmaf(hs[2][k], w, a2);
        a3 = fmaf(hs[3][k], w, a3);
    }
    g_h1[(bg + 0) * M_ + m] = fmaxf(a0, 0.f);
    g_h1[(bg + 1) * M_ + m] = fmaxf(a1, 0.f);
    g_h1[(bg + 2) * M_ + m] = fmaxf(a2, 0.f);
    g_h1[(bg + 3) * M_ + m] = fmaxf(a3, 0.f);
}

__global__ __launch_bounds__(256)
void mlp2_kernel(const float* __restrict__ W2, const float* __restrict__ b2)
{
    __shared__ float hs[4][M_];                 // 32 KB
    const int bg = blockIdx.y * 4, tid = threadIdx.x;
    #pragma unroll
    for (int i = 0; i < 32; i++) {
        const int idx = tid + i * 256;          // < 8192
        hs[idx >> 11][idx & 2047] = g_h1[(bg + (idx >> 11)) * M_ + (idx & 2047)];
    }
    __syncthreads();
    const int m = blockIdx.x * 256 + tid;
    float a0 = b2[m], a1 = a0, a2 = a0, a3 = a0;
    #pragma unroll 8
    for (int k = 0; k < M_; k++) {
        const float w = W2[(size_t)k * M_ + m];
        a0 = fmaf(hs[0][k], w, a0);
        a1 = fmaf(hs[1][k], w, a1);
        a2 = fmaf(hs[2][k], w, a2);
        a3 = fmaf(hs[3][k], w, a3);
    }
    g_h2[(bg + 0) * M_ + m] = fmaxf(a0, 0.f);
    g_h2[(bg + 1) * M_ + m] = fmaxf(a1, 0.f);
    g_h2[(bg + 2) * M_ + m] = fmaxf(a2, 0.f);
    g_h2[(bg + 3) * M_ + m] = fmaxf(a3, 0.f);
}

__global__ void mlp3_kernel(const float* __restrict__ W3, const float* __restrict__ b3,
                            float* __restrict__ out)
{
    const int w = threadIdx.x >> 5, lane = threadIdx.x & 31;
    float acc = 0.f;
    #pragma unroll
    for (int i = 0; i < M_ / 32; i++)
        acc = fmaf(g_h2[w * M_ + lane + i * 32], W3[lane + i * 32], acc);
    #pragma unroll
    for (int off = 16; off; off >>= 1) acc += __shfl_xor_sync(0xffffffffu, acc, off);
    if (lane == 0) out[w] = acc + b3[0];
}

// ---------------------------------------------------------------------------
// Entry. Output layout: (out, q, k) flat: [0,16) out, then q, then k.
// qk_mma is the 4th launch -> ncu profiles the GEMM this round.
// ---------------------------------------------------------------------------
extern "C" void kernel_launch(void* const* d_in, const int* in_sizes, int n_in,
                              void* d_out, int out_size)
{
    const float* x     = (const float*)d_in[0];
    const float* W_qkv = (const float*)d_in[1];
    const float* b_qkv = (const float*)d_in[2];
    const float* W1    = (const float*)d_in[3];
    const float* b1    = (const float*)d_in[4];
    const float* W2    = (const float*)d_in[5];
    const float* b2    = (const float*)d_in[6];
    const float* W3    = (const float*)d_in[7];
    const float* b3    = (const float*)d_in[8];

    float* out   = (float*)d_out;
    float* q_out = out + 16;
    float* k_out = out + 16 + (size_t)NROWS * D_;

    cudaFuncSetAttribute(qk_mma, cudaFuncAttributeMaxDynamicSharedMemorySize, QKV_SMEM);

    qlast_kernel<<<B_, 512>>>(x, W_qkv, b_qkv);                     // 1
    u_kernel<<<dim3(D_ / 8, B_), 256>>>(W_qkv);                     // 2
    scores_cvt_kernel<<<NROWS / 8, 256>>>(x, W_qkv);                // 3 (x->fp16, W->fp16, scores)
    qk_mma<<<dim3(NQK / TN, NROWS / TM), 256, QKV_SMEM>>>(b_qkv, q_out, k_out); // 4 (ncu)
    softmax_kernel<<<B_, 512>>>();
    y_part_kernel<<<dim3(B_, 32), 512>>>(x);
    y_reduce_kernel<<<B_, D_>>>();
    h_kernel<<<B_, 512>>>(x, W_qkv, b_qkv);
    mlp1_kernel<<<dim3(M_ / 256, B_ / 4), 256>>>(W1, b1);
    mlp2_kernel<<<dim3(M_ / 256, B_ / 4), 256>>>(W2, b2);
    mlp3_kernel<<<1, 512>>>(W3, b3, out);
}

// round 12
// speedup vs baseline: 2.1781x; 1.0109x over previous
#include <cuda_runtime.h>
#include <cuda_fp16.h>
#include <cstdint>

// Problem dims
constexpr int B_ = 16, S_ = 4096, D_ = 512, M_ = 2048;
constexpr int NROWS = B_ * S_;   // 65536
constexpr int NQK   = 2 * D_;    // 1024 (q and k only; v never materialized)

// ---------------------------------------------------------------------------
// Scratch (device globals: no allocations allowed)
// ---------------------------------------------------------------------------
__device__ __half g_xh[(size_t)NROWS * D_];        // x in fp16
__device__ __half g_wh[(size_t)NQK * D_];          // W_qk^T fp16 [n][k]
__device__ float g_ql[B_ * D_];                    // q_last (fp32 exact)
__device__ float g_u[B_ * D_];                     // W_k @ q_last
__device__ float g_c[B_];                          // q_last . b_k
__device__ float g_scores[NROWS];
__device__ float g_attn[NROWS];
__device__ float g_part[B_ * 32 * D_];
__device__ float g_y[B_ * D_];
__device__ float g_h[B_ * D_];
__device__ float g_h1[B_ * M_];
__device__ float g_h2[B_ * M_];

// ---------------------------------------------------------------------------
// Helpers (baseline PTX: ldmatrix / mma.sync / cp.async — sm_80+)
// ---------------------------------------------------------------------------
__device__ __forceinline__ uint32_t smem_u32(const void* p) {
    uint32_t a;
    asm("{ .reg .u64 t; cvta.to.shared.u64 t, %1; cvt.u32.u64 %0, t; }"
        : "=r"(a) : "l"(p));
    return a;
}

// Swizzle<3,4,3> for 128-byte rows: bits[6:4] ^= bits[9:7]
#define SWZ128(o) ((o) ^ ((((uint32_t)(o)) >> 3) & 0x70u))

__device__ __forceinline__ void cp_async16(uint32_t sdst, const void* gsrc) {
    asm volatile("cp.async.cg.shared.global [%0], [%1], 16;"
                 :: "r"(sdst), "l"(gsrc) : "memory");
}
#define CP_COMMIT() asm volatile("cp.async.commit_group;" ::: "memory")
#define CP_WAIT(n)  asm volatile("cp.async.wait_group %0;" :: "n"(n) : "memory")

__device__ __forceinline__ void ldm_x4(uint32_t* r, uint32_t addr) {
    asm volatile("ldmatrix.sync.aligned.m8n8.x4.shared.b16 {%0,%1,%2,%3}, [%4];"
                 : "=r"(r[0]), "=r"(r[1]), "=r"(r[2]), "=r"(r[3]) : "r"(addr));
}

__device__ __forceinline__ void mma_f32acc(float* c, const uint32_t* a, const uint32_t* b) {
    asm volatile(
        "mma.sync.aligned.m16n8k16.row.col.f32.f16.f16.f32 "
        "{%0,%1,%2,%3}, {%4,%5,%6,%7}, {%8,%9}, {%0,%1,%2,%3};"
        : "+f"(c[0]), "+f"(c[1]), "+f"(c[2]), "+f"(c[3])
        : "r"(a[0]), "r"(a[1]), "r"(a[2]), "r"(a[3]), "r"(b[0]), "r"(b[1]));
}

// ---------------------------------------------------------------------------
// fp32 exact path pieces (output 0)
// ---------------------------------------------------------------------------
__global__ __launch_bounds__(512)
void qlast_kernel(const float* __restrict__ x, const float* __restrict__ W,
                  const float* __restrict__ bq)
{
    __shared__ float xs[D_];
    __shared__ float red[D_];
    const int b = blockIdx.x, d = threadIdx.x;

    xs[d] = x[((size_t)b * S_ + (S_ - 1)) * D_ + d];
    __syncthreads();

    float acc = bq[d];
    #pragma unroll 8
    for (int k = 0; k < D_; k++) acc = fmaf(xs[k], W[(size_t)k * 1536 + d], acc);
    g_ql[b * D_ + d] = acc;

    red[d] = acc * bq[512 + d];
    __syncthreads();
    for (int s = 256; s; s >>= 1) {
        if (d < s) red[d] += red[d + s];
        __syncthreads();
    }
    if (d == 0) g_c[b] = red[0];
}

// u[b][j] = sum_k W_k[j][k] * q_last[b][k] — warp per j, lanes over k
__global__ __launch_bounds__(256)
void u_kernel(const float* __restrict__ W)
{
    __shared__ float qs[D_];
    const int b = blockIdx.y, tid = threadIdx.x;
    const int warp = tid >> 5, lane = tid & 31;
    qs[tid]       = g_ql[b * D_ + tid];
    qs[tid + 256] = g_ql[b * D_ + tid + 256];
    __syncthreads();

    const int j = blockIdx.x * 8 + warp;
    const float* wrow = W + (size_t)j * 1536 + 512;
    float acc = 0.f;
    #pragma unroll
    for (int i = 0; i < 16; i++)
        acc = fmaf(wrow[lane + i * 32], qs[lane + i * 32], acc);
    #pragma unroll
    for (int off = 16; off; off >>= 1) acc += __shfl_xor_sync(0xffffffffu, acc, off);
    if (lane == 0) g_u[b * D_ + j] = acc;
}

// ---------------------------------------------------------------------------
// scores + convert fusion
// ---------------------------------------------------------------------------
__global__ void scores_cvt_kernel(const float* __restrict__ x,
                                  const float* __restrict__ W)
{
    const int gtid = blockIdx.x * 256 + threadIdx.x;
    if (gtid < D_ * NQK) {
        const int k = gtid >> 10, n = gtid & 1023;
        g_wh[(size_t)n * D_ + k] = __float2half_rn(W[(size_t)k * 1536 + n]);
    }

    const int gw   = (blockIdx.x * blockDim.x + threadIdx.x) >> 5;
    const int lane = threadIdx.x & 31;
    const int b    = gw >> 12;

    const float4* ur = (const float4*)(g_u + b * D_);
    const float4* xr = (const float4*)(x + (size_t)gw * D_);
    __half2* xo = (__half2*)(g_xh + (size_t)gw * D_);

    float acc = 0.f;
    #pragma unroll
    for (int it = 0; it < 4; it++) {
        const int e4 = lane + it * 32;
        float4 uv = ur[e4];
        float4 xv = xr[e4];
        acc += uv.x * xv.x + uv.y * xv.y + uv.z * xv.z + uv.w * xv.w;
        __half2 h0 = __halves2half2(__float2half_rn(xv.x), __float2half_rn(xv.y));
        __half2 h1 = __halves2half2(__float2half_rn(xv.z), __float2half_rn(xv.w));
        xo[e4 * 2]     = h0;
        xo[e4 * 2 + 1] = h1;
    }
    #pragma unroll
    for (int off = 16; off; off >>= 1) acc += __shfl_xor_sync(0xffffffffu, acc, off);
    if (lane == 0) g_scores[gw] = acc + g_c[b];
}

// ---------------------------------------------------------------------------
// QK GEMM via single-pass fp16 mma.sync (fp32 accumulators):
//   C[65536 x 1024] = x[65536 x 512] @ W_qk[512 x 1024] + b
// CTA tile 128x128, warp tile 64x32 (8 warps, 2Mx4N), K-chunk 64 (SW128),
// 3-stage cp.async pipeline, 96KB dynamic smem, 2 CTAs/SM.
// Warp tile 64x32 cuts LDSM bytes/FLOP 25% vs 32x32 (L1 was the 76.8% pipe).
// ---------------------------------------------------------------------------
constexpr int TM = 128, TN = 128, TK = 64;
constexpr int NCHUNK = D_ / TK;  // 8
constexpr int A_TILE = 128 * 128;                      // 16 KB
constexpr int B_TILE = 128 * 128;                      // 16 KB
constexpr int OFF_AH = 0;
constexpr int OFF_BH = OFF_AH + A_TILE;
constexpr int STAGE_BYTES = OFF_BH + B_TILE;           // 32 KB
constexpr int QKV_SMEM    = 3 * STAGE_BYTES;           // 96 KB dynamic

__global__ __launch_bounds__(256, 2)
void qk_mma(const float* __restrict__ bias,
            float* __restrict__ q_out, float* __restrict__ k_out)
{
    extern __shared__ __align__(128) uint8_t sm[];
    const uint32_t sb = smem_u32(sm);

    const int tid  = threadIdx.x;
    const int warp = tid >> 5, lane = tid & 31;
    const int n0 = blockIdx.x * TN;
    const int m0 = blockIdx.y * TM;
    const int wm = (warp & 1) * 64;        // warp row offset (0 or 64)
    const int wn = (warp >> 1) * 32;       // warp col offset (0..96)

    // cp.async coords: rows of 128B = 8 chunks of 16B
    const int rl = tid >> 3;               // 0..31 row group base
    const int cl = tid & 7;                // 16B col 0..7

    auto load_stage = [&](int stage, int ch) {
        const uint32_t s0 = sb + stage * STAGE_BYTES;
        const int kcol = ch * TK + cl * 8;
        #pragma unroll
        for (int j = 0; j < 4; j++) {
            const int row = rl + j * 32;
            const uint32_t so = SWZ128((uint32_t)row * 128 + cl * 16);
            cp_async16(s0 + OFF_AH + so, g_xh + (size_t)(m0 + row) * D_ + kcol);
            cp_async16(s0 + OFF_BH + so, g_wh + (size_t)(n0 + row) * D_ + kcol);
        }
    };

    float acc[4][4][4];
    #pragma unroll
    for (int i = 0; i < 4; i++)
        #pragma unroll
        for (int j = 0; j < 4; j++)
            #pragma unroll
            for (int e = 0; e < 4; e++) acc[i][j][e] = 0.f;

    // ldmatrix lane addressing components
    const uint32_t a_row = (lane & 15);                       // + wm + mf*16
    const uint32_t a_byt = (lane >> 4) << 4;                  // + kk*32
    const uint32_t b_row = ((lane >> 4) << 3) + (lane & 7);   // + wn + p*16
    const uint32_t b_byt = ((lane >> 3) & 1) << 4;            // + kk*32

    load_stage(0, 0); CP_COMMIT();
    load_stage(1, 1); CP_COMMIT();

    for (int ch = 0; ch < NCHUNK; ch++) {
        if (ch + 2 < NCHUNK) {
            load_stage((ch + 2) % 3, ch + 2); CP_COMMIT();
            CP_WAIT(2);
        } else {
            CP_WAIT(0);
        }
        __syncthreads();

        const uint32_t s0 = sb + (ch % 3) * STAGE_BYTES;

        #pragma unroll
        for (int kk = 0; kk < 4; kk++) {
            uint32_t ah[4][4];
            #pragma unroll
            for (int mf = 0; mf < 4; mf++) {
                const uint32_t ra = SWZ128((uint32_t)(wm + mf * 16 + a_row) * 128
                                           + kk * 32 + a_byt);
                ldm_x4(ah[mf], s0 + OFF_AH + ra);
            }
            uint32_t bh[4][2];
            #pragma unroll
            for (int p = 0; p < 2; p++) {
                const uint32_t rb = SWZ128((uint32_t)(wn + p * 16 + b_row) * 128
                                           + kk * 32 + b_byt);
                uint32_t t[4];
                ldm_x4(t, s0 + OFF_BH + rb);
                bh[p * 2][0] = t[0]; bh[p * 2][1] = t[1];
                bh[p * 2 + 1][0] = t[2]; bh[p * 2 + 1][1] = t[3];
            }
            #pragma unroll
            for (int mf = 0; mf < 4; mf++)
                #pragma unroll
                for (int nf = 0; nf < 4; nf++) mma_f32acc(acc[mf][nf], ah[mf], bh[nf]);
        }
        __syncthreads();
    }

    // Epilogue: acc + bias -> float2 global stores, route q/k per CTA
    const int region = n0 >> 9;                 // 0=q, 1=k (TN=128 divides 512)
    float* dst = region ? k_out : q_out;
    const int cbase = n0 - region * 512;

    #pragma unroll
    for (int mf = 0; mf < 4; mf++) {
        #pragma unroll
        for (int nf = 0; nf < 4; nf++) {
            const int colg = n0 + wn + nf * 8 + (lane & 3) * 2;
            const float2 bv = *(const float2*)(bias + colg);
            const int col = cbase + wn + nf * 8 + (lane & 3) * 2;
            const int r0 = m0 + wm + mf * 16 + (lane >> 2);
            float2 v0 = make_float2(acc[mf][nf][0] + bv.x, acc[mf][nf][1] + bv.y);
            float2 v1 = make_float2(acc[mf][nf][2] + bv.x, acc[mf][nf][3] + bv.y);
            *(float2*)(dst + (size_t)r0 * D_ + col)       = v0;
            *(float2*)(dst + (size_t)(r0 + 8) * D_ + col) = v1;
        }
    }
}

// ---------------------------------------------------------------------------
// softmax over S per batch
// ---------------------------------------------------------------------------
__global__ void softmax_kernel()
{
    __shared__ float red[512];
    const int b = blockIdx.x, tid = threadIdx.x;
    const float* sc = g_scores + (size_t)b * S_;

    float lm = -1e30f;
    for (int i = tid; i < S_; i += 512) lm = fmaxf(lm, sc[i]);
    red[tid] = lm; __syncthreads();
    for (int s = 256; s; s >>= 1) {
        if (tid < s) red[tid] = fmaxf(red[tid], red[tid + s]);
        __syncthreads();
    }
    const float mx = red[0];
    __syncthreads();

    float ls = 0.f;
    for (int i = tid; i < S_; i += 512) {
        float e = expf(sc[i] - mx);
        g_attn[(size_t)b * S_ + i] = e;
        ls += e;
    }
    red[tid] = ls; __syncthreads();
    for (int s = 256; s; s >>= 1) {
        if (tid < s) red[tid] += red[tid + s];
        __syncthreads();
    }
    const float inv = 1.f / red[0];
    for (int i = tid; i < S_; i += 512) g_attn[(size_t)b * S_ + i] *= inv;
}

// y[b] = sum_s attn[b,s] * x[b,s]
__global__ void y_part_kernel(const float* __restrict__ x)
{
    const int b = blockIdx.x, ch = blockIdx.y, d = threadIdx.x;
    const float* xp = x + ((size_t)b * S_ + ch * 128) * D_ + d;
    const float* ap = g_attn + (size_t)b * S_ + ch * 128;
    float a0 = 0.f, a1 = 0.f;
    #pragma unroll 8
    for (int s = 0; s < 128; s += 2) {
        a0 = fmaf(ap[s],     xp[(size_t)s * D_],        a0);
        a1 = fmaf(ap[s + 1], xp[(size_t)(s + 1) * D_],  a1);
    }
    g_part[(b * 32 + ch) * D_ + d] = a0 + a1;
}

__global__ void y_reduce_kernel()
{
    const int b = blockIdx.x, d = threadIdx.x;
    float acc = 0.f;
    #pragma unroll
    for (int ch = 0; ch < 32; ch++) acc += g_part[(b * 32 + ch) * D_ + d];
    g_y[b * D_ + d] = acc;
}

// h[b] = x[b,S-1] + y[b] @ W_v + b_v
__global__ __launch_bounds__(512)
void h_kernel(const float* __restrict__ x, const float* __restrict__ W,
              const float* __restrict__ bq)
{
    __shared__ float ys[D_];
    const int b = blockIdx.x, d = threadIdx.x;
    ys[d] = g_y[b * D_ + d];
    __syncthreads();
    float acc = x[((size_t)b * S_ + (S_ - 1)) * D_ + d] + bq[1024 + d];
    #pragma unroll 8
    for (int k = 0; k < D_; k++) acc = fmaf(ys[k], W[(size_t)k * 1536 + 1024 + d], acc);
    g_h[b * D_ + d] = acc;
}

// ---------------------------------------------------------------------------
// MLP layers (fp32), batch-tiled: 4 batches per weight read
// ---------------------------------------------------------------------------
__global__ __launch_bounds__(256)
void mlp1_kernel(const float* __restrict__ W1, const float* __restrict__ b1)
{
    __shared__ float hs[4][D_];
    const int bg = blockIdx.y * 4, tid = threadIdx.x;
    #pragma unroll
    for (int i = 0; i < 8; i++) {
        const int idx = tid + i * 256;          // < 2048
        hs[idx >> 9][idx & 511] = g_h[(bg + (idx >> 9)) * D_ + (idx & 511)];
    }
    __syncthreads();
    const int m = blockIdx.x * 256 + tid;
    float a0 = b1[m], a1 = a0, a2 = a0, a3 = a0;
    #pragma unroll 8
    for (int k = 0; k < D_; k++) {
        const float w = W1[(size_t)k * M_ + m];
        a0 = fmaf(hs[0][k], w, a0);
        a1 = fmaf(hs[1][k], w, a1);
        a2 = fmaf(hs[2][k], w, a2);
        a3 = fmaf(hs[3][k], w, a3);
    }
    g_h1[(bg + 0) * M_ + m] = fmaxf(a0, 0.f);
    g_h1[(bg + 1) * M_ + m] = fmaxf(a1, 0.f);
    g_h1[(bg + 2) * M_ + m] = fmaxf(a2, 0.f);
    g_h1[(bg + 3) * M_ + m] = fmaxf(a3, 0.f);
}

__global__ __launch_bounds__(256)
void mlp2_kernel(const float* __restrict__ W2, const float* __restrict__ b2)
{
    __shared__ float hs[4][M_];                 // 32 KB
    const int bg = blockIdx.y * 4, tid = threadIdx.x;
    #pragma unroll
    for (int i = 0; i < 32; i++) {
        const int idx = tid + i * 256;          // < 8192
        hs[idx >> 11][idx & 2047] = g_h1[(bg + (idx >> 11)) * M_ + (idx & 2047)];
    }
    __syncthreads();
    const int m = blockIdx.x * 256 + tid;
    float a0 = b2[m], a1 = a0, a2 = a0, a3 = a0;
    #pragma unroll 8
    for (int k = 0; k < M_; k++) {
        const float w = W2[(size_t)k * M_ + m];
        a0 = fmaf(hs[0][k], w, a0);
        a1 = fmaf(hs[1][k], w, a1);
        a2 = fmaf(hs[2][k], w, a2);
        a3 = fmaf(hs[3][k], w, a3);
    }
    g_h2[(bg + 0) * M_ + m] = fmaxf(a0, 0.f);
    g_h2[(bg + 1) * M_ + m] = fmaxf(a1, 0.f);
    g_h2[(bg + 2) * M_ + m] = fmaxf(a2, 0.f);
    g_h2[(bg + 3) * M_ + m] = fmaxf(a3, 0.f);
}

__global__ void mlp3_kernel(const float* __restrict__ W3, const float* __restrict__ b3,
                            float* __restrict__ out)
{
    const int w = threadIdx.x >> 5, lane = threadIdx.x & 31;
    float acc = 0.f;
    #pragma unroll
    for (int i = 0; i < M_ / 32; i++)
        acc = fmaf(g_h2[w * M_ + lane + i * 32], W3[lane + i * 32], acc);
    #pragma unroll
    for (int off = 16; off; off >>= 1) acc += __shfl_xor_sync(0xffffffffu, acc, off);
    if (lane == 0) out[w] = acc + b3[0];
}

// ---------------------------------------------------------------------------
// Entry. Output layout: (out, q, k) flat: [0,16) out, then q, then k.
// qk_mma is the 4th launch -> ncu profiles the GEMM.
// ---------------------------------------------------------------------------
extern "C" void kernel_launch(void* const* d_in, const int* in_sizes, int n_in,
                              void* d_out, int out_size)
{
    const float* x     = (const float*)d_in[0];
    const float* W_qkv = (const float*)d_in[1];
    const float* b_qkv = (const float*)d_in[2];
    const float* W1    = (const float*)d_in[3];
    const float* b1    = (const float*)d_in[4];
    const float* W2    = (const float*)d_in[5];
    const float* b2    = (const float*)d_in[6];
    const float* W3    = (const float*)d_in[7];
    const float* b3    = (const float*)d_in[8];

    float* out   = (float*)d_out;
    float* q_out = out + 16;
    float* k_out = out + 16 + (size_t)NROWS * D_;

    cudaFuncSetAttribute(qk_mma, cudaFuncAttributeMaxDynamicSharedMemorySize, QKV_SMEM);

    qlast_kernel<<<B_, 512>>>(x, W_qkv, b_qkv);                     // 1
    u_kernel<<<dim3(D_ / 8, B_), 256>>>(W_qkv);                     // 2
    scores_cvt_kernel<<<NROWS / 8, 256>>>(x, W_qkv);                // 3
    qk_mma<<<dim3(NQK / TN, NROWS / TM), 256, QKV_SMEM>>>(b_qkv, q_out, k_out); // 4 (ncu)
    softmax_kernel<<<B_, 512>>>();
    y_part_kernel<<<dim3(B_, 32), 512>>>(x);
    y_reduce_kernel<<<B_, D_>>>();
    h_kernel<<<B_, 512>>>(x, W_qkv, b_qkv);
    mlp1_kernel<<<dim3(M_ / 256, B_ / 4), 256>>>(W1, b1);
    mlp2_kernel<<<dim3(M_ / 256, B_ / 4), 256>>>(W2, b2);
    mlp3_kernel<<<1, 512>>>(W3, b3, out);
}

// round 13
// speedup vs baseline: 2.4982x; 1.1470x over previous
#include <cuda_runtime.h>
#include <cuda_fp16.h>
#include <cstdint>

// Problem dims
constexpr int B_ = 16, S_ = 4096, D_ = 512, M_ = 2048;
constexpr int NROWS = B_ * S_;   // 65536
constexpr int NQK   = 2 * D_;    // 1024 (q and k only; v never materialized)

// ---------------------------------------------------------------------------
// Scratch (device globals: no allocations allowed)
// ---------------------------------------------------------------------------
__device__ __half g_xh[(size_t)NROWS * D_];        // x in fp16
__device__ __half g_wh[(size_t)NQK * D_];          // W_qk^T fp16 [n][k]
__device__ float g_ql[B_ * D_];                    // q_last (fp32 exact)
__device__ float g_u[B_ * D_];                     // W_k @ q_last
__device__ float g_c[B_];                          // q_last . b_k
__device__ float g_mx[B_];                         // softmax max
__device__ float g_sum[B_];                        // softmax denom
__device__ float g_scores[NROWS];
__device__ float g_part[B_ * 32 * D_];
__device__ float g_h[B_ * D_];
__device__ float g_h1[B_ * M_];
__device__ float g_m2p[4][B_ * M_];                // mlp2 k-split partials
__device__ float g_h2[B_ * M_];

// ---------------------------------------------------------------------------
// Helpers (baseline PTX: ldmatrix / mma.sync / cp.async — sm_80+)
// ---------------------------------------------------------------------------
__device__ __forceinline__ uint32_t smem_u32(const void* p) {
    uint32_t a;
    asm("{ .reg .u64 t; cvta.to.shared.u64 t, %1; cvt.u32.u64 %0, t; }"
        : "=r"(a) : "l"(p));
    return a;
}

// Swizzle<3,4,3> for 128-byte rows: bits[6:4] ^= bits[9:7]
#define SWZ128(o) ((o) ^ ((((uint32_t)(o)) >> 3) & 0x70u))

__device__ __forceinline__ void cp_async16(uint32_t sdst, const void* gsrc) {
    asm volatile("cp.async.cg.shared.global [%0], [%1], 16;"
                 :: "r"(sdst), "l"(gsrc) : "memory");
}
#define CP_COMMIT() asm volatile("cp.async.commit_group;" ::: "memory")
#define CP_WAIT(n)  asm volatile("cp.async.wait_group %0;" :: "n"(n) : "memory")

__device__ __forceinline__ void ldm_x4(uint32_t* r, uint32_t addr) {
    asm volatile("ldmatrix.sync.aligned.m8n8.x4.shared.b16 {%0,%1,%2,%3}, [%4];"
                 : "=r"(r[0]), "=r"(r[1]), "=r"(r[2]), "=r"(r[3]) : "r"(addr));
}

__device__ __forceinline__ void mma_f32acc(float* c, const uint32_t* a, const uint32_t* b) {
    asm volatile(
        "mma.sync.aligned.m16n8k16.row.col.f32.f16.f16.f32 "
        "{%0,%1,%2,%3}, {%4,%5,%6,%7}, {%8,%9}, {%0,%1,%2,%3};"
        : "+f"(c[0]), "+f"(c[1]), "+f"(c[2]), "+f"(c[3])
        : "r"(a[0]), "r"(a[1]), "r"(a[2]), "r"(a[3]), "r"(b[0]), "r"(b[1]));
}

// ---------------------------------------------------------------------------
// fp32 exact path pieces (output 0)
// ---------------------------------------------------------------------------
__global__ __launch_bounds__(512)
void qlast_kernel(const float* __restrict__ x, const float* __restrict__ W,
                  const float* __restrict__ bq)
{
    __shared__ float xs[D_];
    __shared__ float red[D_];
    const int b = blockIdx.x, d = threadIdx.x;

    xs[d] = x[((size_t)b * S_ + (S_ - 1)) * D_ + d];
    __syncthreads();

    float acc = bq[d];
    #pragma unroll 8
    for (int k = 0; k < D_; k++) acc = fmaf(xs[k], W[(size_t)k * 1536 + d], acc);
    g_ql[b * D_ + d] = acc;

    red[d] = acc * bq[512 + d];
    __syncthreads();
    for (int s = 256; s; s >>= 1) {
        if (d < s) red[d] += red[d + s];
        __syncthreads();
    }
    if (d == 0) g_c[b] = red[0];
}

// u[b][j] = sum_k W_k[j][k] * q_last[b][k] — warp per j, lanes over k
__global__ __launch_bounds__(256)
void u_kernel(const float* __restrict__ W)
{
    __shared__ float qs[D_];
    const int b = blockIdx.y, tid = threadIdx.x;
    const int warp = tid >> 5, lane = tid & 31;
    qs[tid]       = g_ql[b * D_ + tid];
    qs[tid + 256] = g_ql[b * D_ + tid + 256];
    __syncthreads();

    const int j = blockIdx.x * 8 + warp;
    const float* wrow = W + (size_t)j * 1536 + 512;
    float acc = 0.f;
    #pragma unroll
    for (int i = 0; i < 16; i++)
        acc = fmaf(wrow[lane + i * 32], qs[lane + i * 32], acc);
    #pragma unroll
    for (int off = 16; off; off >>= 1) acc += __shfl_xor_sync(0xffffffffu, acc, off);
    if (lane == 0) g_u[b * D_ + j] = acc;
}

// W_qk^T -> fp16 (separate so scores_cvt sits at profiler slot 4)
__global__ void convert_w(const float* __restrict__ W)
{
    const int e = blockIdx.x * blockDim.x + threadIdx.x;   // < 512*1024
    const int k = e >> 10, n = e & 1023;
    g_wh[(size_t)n * D_ + k] = __float2half_rn(W[(size_t)k * 1536 + n]);
}

// ---------------------------------------------------------------------------
// scores + x->fp16 fusion (profiled this round at slot 4)
// ---------------------------------------------------------------------------
__global__ void scores_cvt_kernel(const float* __restrict__ x)
{
    const int gw   = (blockIdx.x * blockDim.x + threadIdx.x) >> 5;
    const int lane = threadIdx.x & 31;
    const int b    = gw >> 12;

    const float4* ur = (const float4*)(g_u + b * D_);
    const float4* xr = (const float4*)(x + (size_t)gw * D_);
    __half2* xo = (__half2*)(g_xh + (size_t)gw * D_);

    float acc = 0.f;
    #pragma unroll
    for (int it = 0; it < 4; it++) {
        const int e4 = lane + it * 32;
        float4 uv = ur[e4];
        float4 xv = xr[e4];
        acc += uv.x * xv.x + uv.y * xv.y + uv.z * xv.z + uv.w * xv.w;
        __half2 h0 = __halves2half2(__float2half_rn(xv.x), __float2half_rn(xv.y));
        __half2 h1 = __halves2half2(__float2half_rn(xv.z), __float2half_rn(xv.w));
        xo[e4 * 2]     = h0;
        xo[e4 * 2 + 1] = h1;
    }
    #pragma unroll
    for (int off = 16; off; off >>= 1) acc += __shfl_xor_sync(0xffffffffu, acc, off);
    if (lane == 0) g_scores[gw] = acc + g_c[b];
}

// ---------------------------------------------------------------------------
// QK GEMM (unchanged from round 12): CTA 128x128, warp 64x32, TK=64, 3-stage
// ---------------------------------------------------------------------------
constexpr int TM = 128, TN = 128, TK = 64;
constexpr int NCHUNK = D_ / TK;  // 8
constexpr int A_TILE = 128 * 128;
constexpr int B_TILE = 128 * 128;
constexpr int OFF_AH = 0;
constexpr int OFF_BH = OFF_AH + A_TILE;
constexpr int STAGE_BYTES = OFF_BH + B_TILE;           // 32 KB
constexpr int QKV_SMEM    = 3 * STAGE_BYTES;           // 96 KB dynamic

__global__ __launch_bounds__(256, 2)
void qk_mma(const float* __restrict__ bias,
            float* __restrict__ q_out, float* __restrict__ k_out)
{
    extern __shared__ __align__(128) uint8_t sm[];
    const uint32_t sb = smem_u32(sm);

    const int tid  = threadIdx.x;
    const int warp = tid >> 5, lane = tid & 31;
    const int n0 = blockIdx.x * TN;
    const int m0 = blockIdx.y * TM;
    const int wm = (warp & 1) * 64;
    const int wn = (warp >> 1) * 32;

    const int rl = tid >> 3;
    const int cl = tid & 7;

    auto load_stage = [&](int stage, int ch) {
        const uint32_t s0 = sb + stage * STAGE_BYTES;
        const int kcol = ch * TK + cl * 8;
        #pragma unroll
        for (int j = 0; j < 4; j++) {
            const int row = rl + j * 32;
            const uint32_t so = SWZ128((uint32_t)row * 128 + cl * 16);
            cp_async16(s0 + OFF_AH + so, g_xh + (size_t)(m0 + row) * D_ + kcol);
            cp_async16(s0 + OFF_BH + so, g_wh + (size_t)(n0 + row) * D_ + kcol);
        }
    };

    float acc[4][4][4];
    #pragma unroll
    for (int i = 0; i < 4; i++)
        #pragma unroll
        for (int j = 0; j < 4; j++)
            #pragma unroll
            for (int e = 0; e < 4; e++) acc[i][j][e] = 0.f;

    const uint32_t a_row = (lane & 15);
    const uint32_t a_byt = (lane >> 4) << 4;
    const uint32_t b_row = ((lane >> 4) << 3) + (lane & 7);
    const uint32_t b_byt = ((lane >> 3) & 1) << 4;

    load_stage(0, 0); CP_COMMIT();
    load_stage(1, 1); CP_COMMIT();

    for (int ch = 0; ch < NCHUNK; ch++) {
        if (ch + 2 < NCHUNK) {
            load_stage((ch + 2) % 3, ch + 2); CP_COMMIT();
            CP_WAIT(2);
        } else {
            CP_WAIT(0);
        }
        __syncthreads();

        const uint32_t s0 = sb + (ch % 3) * STAGE_BYTES;

        #pragma unroll
        for (int kk = 0; kk < 4; kk++) {
            uint32_t ah[4][4];
            #pragma unroll
            for (int mf = 0; mf < 4; mf++) {
                const uint32_t ra = SWZ128((uint32_t)(wm + mf * 16 + a_row) * 128
                                           + kk * 32 + a_byt);
                ldm_x4(ah[mf], s0 + OFF_AH + ra);
            }
            uint32_t bh[4][2];
            #pragma unroll
            for (int p = 0; p < 2; p++) {
                const uint32_t rb = SWZ128((uint32_t)(wn + p * 16 + b_row) * 128
                                           + kk * 32 + b_byt);
                uint32_t t[4];
                ldm_x4(t, s0 + OFF_BH + rb);
                bh[p * 2][0] = t[0]; bh[p * 2][1] = t[1];
                bh[p * 2 + 1][0] = t[2]; bh[p * 2 + 1][1] = t[3];
            }
            #pragma unroll
            for (int mf = 0; mf < 4; mf++)
                #pragma unroll
                for (int nf = 0; nf < 4; nf++) mma_f32acc(acc[mf][nf], ah[mf], bh[nf]);
        }
        __syncthreads();
    }

    const int region = n0 >> 9;
    float* dst = region ? k_out : q_out;
    const int cbase = n0 - region * 512;

    #pragma unroll
    for (int mf = 0; mf < 4; mf++) {
        #pragma unroll
        for (int nf = 0; nf < 4; nf++) {
            const int colg = n0 + wn + nf * 8 + (lane & 3) * 2;
            const float2 bv = *(const float2*)(bias + colg);
            const int col = cbase + wn + nf * 8 + (lane & 3) * 2;
            const int r0 = m0 + wm + mf * 16 + (lane >> 2);
            float2 v0 = make_float2(acc[mf][nf][0] + bv.x, acc[mf][nf][1] + bv.y);
            float2 v1 = make_float2(acc[mf][nf][2] + bv.x, acc[mf][nf][3] + bv.y);
            *(float2*)(dst + (size_t)r0 * D_ + col)       = v0;
            *(float2*)(dst + (size_t)(r0 + 8) * D_ + col) = v1;
        }
    }
}

// ---------------------------------------------------------------------------
// softmax stats only: mx[b], sum[b] (attn array eliminated)
// ---------------------------------------------------------------------------
__global__ void softmax_stats_kernel()
{
    __shared__ float red[512];
    const int b = blockIdx.x, tid = threadIdx.x;
    const float* sc = g_scores + (size_t)b * S_;

    float lm = -1e30f;
    for (int i = tid; i < S_; i += 512) lm = fmaxf(lm, sc[i]);
    red[tid] = lm; __syncthreads();
    for (int s = 256; s; s >>= 1) {
        if (tid < s) red[tid] = fmaxf(red[tid], red[tid + s]);
        __syncthreads();
    }
    const float mx = red[0];
    __syncthreads();

    float ls = 0.f;
    for (int i = tid; i < S_; i += 512) ls += expf(sc[i] - mx);
    red[tid] = ls; __syncthreads();
    for (int s = 256; s; s >>= 1) {
        if (tid < s) red[tid] += red[tid + s];
        __syncthreads();
    }
    if (tid == 0) { g_mx[b] = mx; g_sum[b] = red[0]; }
}

// y partials with inline exp (unnormalized; scaled in h_kernel)
__global__ void y_part_kernel(const float* __restrict__ x)
{
    const int b = blockIdx.x, ch = blockIdx.y, d = threadIdx.x;
    const float* xp = x + ((size_t)b * S_ + ch * 128) * D_ + d;
    const float* sp = g_scores + (size_t)b * S_ + ch * 128;
    const float mx = g_mx[b];
    float a0 = 0.f, a1 = 0.f;
    #pragma unroll 8
    for (int s = 0; s < 128; s += 2) {
        a0 = fmaf(expf(sp[s] - mx),     xp[(size_t)s * D_],       a0);
        a1 = fmaf(expf(sp[s + 1] - mx), xp[(size_t)(s + 1) * D_], a1);
    }
    g_part[(b * 32 + ch) * D_ + d] = a0 + a1;
}

// h[b] = x[b,S-1] + (sum_ch part / sum) @ W_v + b_v   (fused reduce + GEMV)
__global__ __launch_bounds__(512)
void h_kernel(const float* __restrict__ x, const float* __restrict__ W,
              const float* __restrict__ bq)
{
    __shared__ float ys[D_];
    const int b = blockIdx.x, d = threadIdx.x;
    const float inv = 1.f / g_sum[b];
    float yy = 0.f;
    #pragma unroll
    for (int ch = 0; ch < 32; ch++) yy += g_part[(b * 32 + ch) * D_ + d];
    ys[d] = yy * inv;
    __syncthreads();
    float acc = x[((size_t)b * S_ + (S_ - 1)) * D_ + d] + bq[1024 + d];
    #pragma unroll 8
    for (int k = 0; k < D_; k++) acc = fmaf(ys[k], W[(size_t)k * 1536 + 1024 + d], acc);
    g_h[b * D_ + d] = acc;
}

// ---------------------------------------------------------------------------
// MLP layers (fp32), batch-tiled; mlp2 K-split x4 for latency
// ---------------------------------------------------------------------------
__global__ __launch_bounds__(256)
void mlp1_kernel(const float* __restrict__ W1, const float* __restrict__ b1)
{
    __shared__ float hs[4][D_];
    const int bg = blockIdx.y * 4, tid = threadIdx.x;
    #pragma unroll
    for (int i = 0; i < 8; i++) {
        const int idx = tid + i * 256;
        hs[idx >> 9][idx & 511] = g_h[(bg + (idx >> 9)) * D_ + (idx & 511)];
    }
    __syncthreads();
    const int m = blockIdx.x * 256 + tid;
    float a0 = b1[m], a1 = a0, a2 = a0, a3 = a0;
    #pragma unroll 8
    for (int k = 0; k < D_; k++) {
        const float w = W1[(size_t)k * M_ + m];
        a0 = fmaf(hs[0][k], w, a0);
        a1 = fmaf(hs[1][k], w, a1);
        a2 = fmaf(hs[2][k], w, a2);
        a3 = fmaf(hs[3][k], w, a3);
    }
    g_h1[(bg + 0) * M_ + m] = fmaxf(a0, 0.f);
    g_h1[(bg + 1) * M_ + m] = fmaxf(a1, 0.f);
    g_h1[(bg + 2) * M_ + m] = fmaxf(a2, 0.f);
    g_h1[(bg + 3) * M_ + m] = fmaxf(a3, 0.f);
}

// mlp2 partials: grid (m-blocks=8, batch-groups=4, k-splits=4)
__global__ __launch_bounds__(256)
void mlp2_part_kernel(const float* __restrict__ W2)
{
    __shared__ float hs[4][512];
    const int bg = blockIdx.y * 4, kz = blockIdx.z, tid = threadIdx.x;
    const int k0 = kz * 512;
    #pragma unroll
    for (int i = 0; i < 8; i++) {
        const int idx = tid + i * 256;          // < 2048
        hs[idx >> 9][idx & 511] = g_h1[(bg + (idx >> 9)) * M_ + k0 + (idx & 511)];
    }
    __syncthreads();
    const int m = blockIdx.x * 256 + tid;
    float a0 = 0.f, a1 = 0.f, a2 = 0.f, a3 = 0.f;
    #pragma unroll 8
    for (int k = 0; k < 512; k++) {
        const float w = W2[(size_t)(k0 + k) * M_ + m];
        a0 = fmaf(hs[0][k], w, a0);
        a1 = fmaf(hs[1][k], w, a1);
        a2 = fmaf(hs[2][k], w, a2);
        a3 = fmaf(hs[3][k], w, a3);
    }
    g_m2p[kz][(bg + 0) * M_ + m] = a0;
    g_m2p[kz][(bg + 1) * M_ + m] = a1;
    g_m2p[kz][(bg + 2) * M_ + m] = a2;
    g_m2p[kz][(bg + 3) * M_ + m] = a3;
}

__global__ void mlp2_red_kernel(const float* __restrict__ b2)
{
    const int e = blockIdx.x * 256 + threadIdx.x;   // < 16*2048
    const int m = e & (M_ - 1);
    const float v = b2[m] + g_m2p[0][e] + g_m2p[1][e] + g_m2p[2][e] + g_m2p[3][e];
    g_h2[e] = fmaxf(v, 0.f);
}

__global__ void mlp3_kernel(const float* __restrict__ W3, const float* __restrict__ b3,
                            float* __restrict__ out)
{
    const int w = threadIdx.x >> 5, lane = threadIdx.x & 31;
    float acc = 0.f;
    #pragma unroll
    for (int i = 0; i < M_ / 32; i++)
        acc = fmaf(g_h2[w * M_ + lane + i * 32], W3[lane + i * 32], acc);
    #pragma unroll
    for (int off = 16; off; off >>= 1) acc += __shfl_xor_sync(0xffffffffu, acc, off);
    if (lane == 0) out[w] = acc + b3[0];
}

// ---------------------------------------------------------------------------
// Entry. Output layout: (out, q, k) flat: [0,16) out, then q, then k.
// scores_cvt is launch slot 4 -> profiled this round.
// ---------------------------------------------------------------------------
extern "C" void kernel_launch(void* const* d_in, const int* in_sizes, int n_in,
                              void* d_out, int out_size)
{
    const float* x     = (const float*)d_in[0];
    const float* W_qkv = (const float*)d_in[1];
    const float* b_qkv = (const float*)d_in[2];
    const float* W1    = (const float*)d_in[3];
    const float* b1    = (const float*)d_in[4];
    const float* W2    = (const float*)d_in[5];
    const float* b2    = (const float*)d_in[6];
    const float* W3    = (const float*)d_in[7];
    const float* b3    = (const float*)d_in[8];

    float* out   = (float*)d_out;
    float* q_out = out + 16;
    float* k_out = out + 16 + (size_t)NROWS * D_;

    cudaFuncSetAttribute(qk_mma, cudaFuncAttributeMaxDynamicSharedMemorySize, QKV_SMEM);

    qlast_kernel<<<B_, 512>>>(x, W_qkv, b_qkv);                     // 1
    u_kernel<<<dim3(D_ / 8, B_), 256>>>(W_qkv);                     // 2
    convert_w<<<(D_ * NQK) / 256, 256>>>(W_qkv);                    // 3
    scores_cvt_kernel<<<NROWS / 8, 256>>>(x);                       // 4 (ncu probe)
    qk_mma<<<dim3(NQK / TN, NROWS / TM), 256, QKV_SMEM>>>(b_qkv, q_out, k_out); // 5
    softmax_stats_kernel<<<B_, 512>>>();                            // 6
    y_part_kernel<<<dim3(B_, 32), 512>>>(x);                        // 7
    h_kernel<<<B_, 512>>>(x, W_qkv, b_qkv);                         // 8
    mlp1_kernel<<<dim3(M_ / 256, B_ / 4), 256>>>(W1, b1);           // 9
    mlp2_part_kernel<<<dim3(M_ / 256, B_ / 4, 4), 256>>>(W2);       // 10
    mlp2_red_kernel<<<(B_ * M_) / 256, 256>>>(b2);                  // 11
    mlp3_kernel<<<1, 512>>>(W3, b3, out);                           // 12
}